// round 14
// baseline (speedup 1.0000x reference)
#include <cuda_runtime.h>
#include <cuda_bf16.h>
#include <cuda_fp16.h>
#include <cstdint>

#define NB 1024
constexpr int NA = 32;
constexpr int DD = 128;
constexpr int RR = 50;
constexpr int NP = 496;
constexpr int NLAY = 6;
constexpr int TKNOTS = 2048;
constexpr float CUTOFF = 5.0f;
constexpr float WIDTH  = CUTOFF / (RR - 1);
constexpr float COEFF  = -0.5f / (WIDTH * WIDTH);
constexpr float LN2    = 0.69314718055994531f;
constexpr float PIF    = 3.14159265358979323846f;
constexpr float HSTEP  = CUTOFF / (TKNOTS - 1);
constexpr float KSCALE = (TKNOTS - 1) / CUTOFF;
constexpr int BSTR = 272;    // bf16 operand row stride (bytes) = 136 halves

// ---------------- device globals ----------------
// paired filter table: entry k holds (W_k, W_{k+1}) interleaved per 4-ch group.
__device__ __half   g_tab[(size_t)NLAY * TKNOTS * 256];
__device__ uint32_t g_wh[3 * NLAY * DD * (DD / 2)];
__device__ uint32_t g_wl[3 * NLAY * DD * (DD / 2)];

// ---------------- helpers ----------------
__device__ __forceinline__ uint32_t smem_u32(const void* p) {
    uint32_t a;
    asm("{ .reg .u64 t; cvta.to.shared.u64 t, %1; cvt.u32.u64 %0, t; }"
        : "=r"(a) : "l"(p));
    return a;
}
__device__ __forceinline__ void ldsm4(uint32_t* r, uint32_t a) {
    asm volatile("ldmatrix.sync.aligned.m8n8.x4.shared.b16 {%0,%1,%2,%3}, [%4];"
        : "=r"(r[0]), "=r"(r[1]), "=r"(r[2]), "=r"(r[3]) : "r"(a));
}
__device__ __forceinline__ void ldsm4t(uint32_t* r, uint32_t a) {
    asm volatile("ldmatrix.sync.aligned.m8n8.x4.trans.shared.b16 {%0,%1,%2,%3}, [%4];"
        : "=r"(r[0]), "=r"(r[1]), "=r"(r[2]), "=r"(r[3]) : "r"(a));
}
__device__ __forceinline__ void mmabf(float* c, const uint32_t* a, const uint32_t* b) {
    asm volatile("mma.sync.aligned.m16n8k16.row.col.f32.bf16.bf16.f32 "
        "{%0,%1,%2,%3}, {%4,%5,%6,%7}, {%8,%9}, {%0,%1,%2,%3};"
        : "+f"(c[0]), "+f"(c[1]), "+f"(c[2]), "+f"(c[3])
        : "r"(a[0]), "r"(a[1]), "r"(a[2]), "r"(a[3]), "r"(b[0]), "r"(b[1]));
}
__device__ __forceinline__ void split2(float x, uint32_t& h, uint32_t& l) {
    __nv_bfloat16 hb = __float2bfloat16(x);
    __nv_bfloat16 lb = __float2bfloat16(x - __bfloat162float(hb));
    h = (uint32_t)__bfloat16_as_ushort(hb);
    l = (uint32_t)__bfloat16_as_ushort(lb);
}
__device__ __forceinline__ float sspf(float x) {
    float r = __logf(fmaf(0.5f, __expf(x), 0.5f));
    return (x > 20.f) ? x - LN2 : r;
}
__device__ __forceinline__ void fma4(float4& a, float s, const float4& b) {
    a.x = fmaf(s, b.x, a.x); a.y = fmaf(s, b.y, a.y);
    a.z = fmaf(s, b.z, a.z); a.w = fmaf(s, b.w, a.w);
}
__device__ __forceinline__ void fma4v(float4& a, const float4& s, const float4& b) {
    a.x = fmaf(s.x, b.x, a.x); a.y = fmaf(s.y, b.y, a.y);
    a.z = fmaf(s.z, b.z, a.z); a.w = fmaf(s.w, b.w, a.w);
}
__device__ __forceinline__ float comp(const float4& v, int k) { return ((const float*)&v)[k]; }

// lerp paired entry (a01,a23,b01,b23) with half2 arithmetic -> fp32x4
__device__ __forceinline__ float4 lerp_p4(uint4 ab, __half2 f2) {
    __half2 a0 = *reinterpret_cast<__half2*>(&ab.x);
    __half2 a1 = *reinterpret_cast<__half2*>(&ab.y);
    __half2 b0 = *reinterpret_cast<__half2*>(&ab.z);
    __half2 b1 = *reinterpret_cast<__half2*>(&ab.w);
    __half2 w0 = __hfma2(f2, __hsub2(b0, a0), a0);
    __half2 w1 = __hfma2(f2, __hsub2(b1, a1), a1);
    float2 lo = __half22float2(w0), hi = __half22float2(w1);
    return make_float4(lo.x, lo.y, hi.x, hi.y);
}

// 16x16 output warp tile, K=16*KS, 3-pass split-bf16. A[m][k] stride BSTR, B[k][n] stride BSTR.
template<int KS>
__device__ __forceinline__ void gemm16(
    uint32_t aH, uint32_t aL, uint32_t bH, uint32_t bL,
    int mr, int nc, int lane, float (*c)[4])
{
    const uint32_t aoff = (uint32_t)((mr + (lane & 7) + ((lane >> 3) & 1) * 8) * BSTR
                                     + ((lane >> 4) & 1) * 16);
    const uint32_t boff = (uint32_t)(((lane & 7) + ((lane >> 3) & 1) * 8) * BSTR
                                     + (nc + ((lane >> 4) & 1) * 8) * 2);
    #pragma unroll
    for (int ks = 0; ks < KS; ks++) {
        const uint32_t ao = aoff + ks * 32;
        const uint32_t bo = boff + ks * 16 * BSTR;
        uint32_t Ah[4], Al[4], Bh[4], Bl[4];
        ldsm4(Ah, aH + ao);
        ldsm4t(Bh, bH + bo);
        mmabf(c[0], Ah, Bh); mmabf(c[1], Ah, Bh + 2);
        ldsm4t(Bl, bL + bo);
        mmabf(c[0], Ah, Bl); mmabf(c[1], Ah, Bl + 2);
        ldsm4(Al, aL + ao);
        mmabf(c[0], Al, Bh); mmabf(c[1], Al, Bh + 2);
    }
}

// ======= builder 1 (256 thr, 64 knots/CTA, 8 rows/warp), paired output ==========
constexpr int A_W1 = 0;          // 52x128
constexpr int A_W2 = 6656;       // 128x128
constexpr int A_F  = 23040;      // 64x52
constexpr int A_H1 = 26368;      // 64x128
constexpr int A_B1 = 34560;
constexpr int A_B2 = 34688;
constexpr int A_FLOATS = 34816;

__global__ void __launch_bounds__(256, 1)
build_table(const float* __restrict__ Wf1, const float* __restrict__ bf1,
            const float* __restrict__ Wf2, const float* __restrict__ bf2)
{
    extern __shared__ float sa[];
    const int tid = threadIdx.x, lane = tid & 31, w = tid >> 5;   // 8 warps
    const int layer = blockIdx.y;
    const int kb = blockIdx.x * 64;
    const int c4 = lane << 2;

    for (int idx = tid; idx < 52 * 128; idx += 256) {
        int k = idx >> 7, n = idx & 127;
        sa[A_W1 + idx] = (k < RR) ? Wf1[layer * RR * DD + k * DD + n] : 0.f;
    }
    for (int idx = tid; idx < 128 * 128; idx += 256)
        sa[A_W2 + idx] = Wf2[layer * DD * DD + idx];
    if (tid < 128) {
        sa[A_B1 + tid] = bf1[layer * DD + tid];
        sa[A_B2 + tid] = bf2[layer * DD + tid];
    }
    for (int idx = tid; idx < 64 * 52; idx += 256) {
        int row = idx / 52, r = idx - row * 52;
        float d = (float)(kb + row) * HSTEP;
        float t = d - (float)r * WIDTH;
        sa[A_F + idx] = (r < RR) ? __expf(COEFF * t * t) : 0.f;
    }
    __syncthreads();

    for (int blk = 0; blk < 2; blk++) {
        const int r0 = w * 8 + blk * 4;
        float4 ac0 = {0,0,0,0}, ac1 = {0,0,0,0}, ac2 = {0,0,0,0}, ac3 = {0,0,0,0};
        #pragma unroll
        for (int k = 0; k < 52; k += 4) {
            float4 a0 = *(const float4*)(sa + A_F + (r0 + 0) * 52 + k);
            float4 a1 = *(const float4*)(sa + A_F + (r0 + 1) * 52 + k);
            float4 a2 = *(const float4*)(sa + A_F + (r0 + 2) * 52 + k);
            float4 a3 = *(const float4*)(sa + A_F + (r0 + 3) * 52 + k);
            #pragma unroll
            for (int kk = 0; kk < 4; kk++) {
                float4 b = *(const float4*)(sa + A_W1 + (k + kk) * 128 + c4);
                fma4(ac0, comp(a0, kk), b); fma4(ac1, comp(a1, kk), b);
                fma4(ac2, comp(a2, kk), b); fma4(ac3, comp(a3, kk), b);
            }
        }
        float4 bb = *(const float4*)(sa + A_B1 + c4);
        float4* accs[4] = {&ac0, &ac1, &ac2, &ac3};
        #pragma unroll
        for (int m = 0; m < 4; m++) {
            float4 o;
            o.x = sspf(accs[m]->x + bb.x); o.y = sspf(accs[m]->y + bb.y);
            o.z = sspf(accs[m]->z + bb.z); o.w = sspf(accs[m]->w + bb.w);
            *(float4*)(sa + A_H1 + (r0 + m) * 128 + c4) = o;
        }
    }
    __syncthreads();

    char* gt = (char*)g_tab;
    for (int blk = 0; blk < 2; blk++) {
        const int r0 = w * 8 + blk * 4;
        float4 ac0 = {0,0,0,0}, ac1 = {0,0,0,0}, ac2 = {0,0,0,0}, ac3 = {0,0,0,0};
        #pragma unroll 4
        for (int k = 0; k < 128; k += 4) {
            float4 a0 = *(const float4*)(sa + A_H1 + (r0 + 0) * 128 + k);
            float4 a1 = *(const float4*)(sa + A_H1 + (r0 + 1) * 128 + k);
            float4 a2 = *(const float4*)(sa + A_H1 + (r0 + 2) * 128 + k);
            float4 a3 = *(const float4*)(sa + A_H1 + (r0 + 3) * 128 + k);
            #pragma unroll
            for (int kk = 0; kk < 4; kk++) {
                float4 b = *(const float4*)(sa + A_W2 + (k + kk) * 128 + c4);
                fma4(ac0, comp(a0, kk), b); fma4(ac1, comp(a1, kk), b);
                fma4(ac2, comp(a2, kk), b); fma4(ac3, comp(a3, kk), b);
            }
        }
        float4 bb = *(const float4*)(sa + A_B2 + c4);
        float4* accs[4] = {&ac0, &ac1, &ac2, &ac3};
        #pragma unroll
        for (int m = 0; m < 4; m++) {
            int rowg = kb + r0 + m;
            float d = (float)rowg * HSTEP;
            float rc = (d < CUTOFF) ? 0.5f * (__cosf(d * (PIF / CUTOFF)) + 1.f) : 0.f;
            float4 o;
            o.x = (accs[m]->x + bb.x) * rc; o.y = (accs[m]->y + bb.y) * rc;
            o.z = (accs[m]->z + bb.z) * rc; o.w = (accs[m]->w + bb.w) * rc;
            __half h0 = __float2half_rn(o.x), h1 = __float2half_rn(o.y);
            __half h2 = __float2half_rn(o.z), h3 = __float2half_rn(o.w);
            uint2 pk;
            pk.x = (uint32_t)__half_as_ushort(h0) | ((uint32_t)__half_as_ushort(h1) << 16);
            pk.y = (uint32_t)__half_as_ushort(h2) | ((uint32_t)__half_as_ushort(h3) << 16);
            size_t eb = ((size_t)layer * TKNOTS + rowg) * 512;
            *(uint2*)(gt + eb + lane * 16) = pk;                   // a-slot of entry rowg
            if (rowg > 0)
                *(uint2*)(gt + eb - 512 + lane * 16 + 8) = pk;     // b-slot of entry rowg-1
        }
    }
}

// ================= builder 2: split Wi/Wo1/Wo2 to bf16 hi/lo =================
__global__ void __launch_bounds__(1024, 1)
build_wsplit(const float* __restrict__ Wi,
             const float* __restrict__ Wo1,
             const float* __restrict__ Wo2)
{
    int idx = blockIdx.x * 1024 + threadIdx.x;
    const int TOT = 3 * NLAY * DD * (DD / 2);
    if (idx >= TOT) return;
    int mat = idx / (NLAY * DD * (DD / 2));
    int rem = idx - mat * (NLAY * DD * (DD / 2));
    const float* src = (mat == 0) ? Wi : (mat == 1) ? Wo1 : Wo2;
    float v0 = src[rem * 2];
    float v1 = src[rem * 2 + 1];
    uint32_t h0, l0, h1, l1;
    split2(v0, h0, l0); split2(v1, h1, l1);
    g_wh[idx] = h0 | (h1 << 16);
    g_wl[idx] = l0 | (l1 << 16);
}

// ================= main kernel: 2 molecules / CTA, 1024 threads =================
constexpr int SB_WBH  = 0;         // 128 x 272B = 34816  (Wi -> Wo1 -> Wo2)
constexpr int SB_WBL  = 34816;     // -> 69632
constexpr int SB_X    = 69632;     // 64x128 f32 = 32768 -> 102400
constexpr int SB_XF   = 102400;    // 32768 -> 135168 (head scratch later)
constexpr int SB_A1H  = 135168;    // 64 x 272B = 17408 -> 152576
constexpr int SB_A1L  = 152576;    // -> 169984
constexpr int SB_A2H  = 169984;    // -> 187392
constexpr int SB_A2L  = 187392;    // -> 204800
constexpr int SB_BO1  = 204800;    // 128 f32 -> 205312
constexpr int SB_BO2  = 205312;    // -> 205824
constexpr int SB_POS  = 205824;    // 192 f32 (pad 1024) -> 206848
constexpr int SB_KOFF = 206848;    // 1024 u32 -> 210944
constexpr int SB_FRACH= 210944;    // 1024 f16 -> 212992
constexpr int SB_PAIR = 212992;    // 512 u16 -> 214016
constexpr int SB_ENT  = 214016;    // 2 x 32 x 31 x 8B = 15872 -> 229888
constexpr int SMEM_BYTES = 229888;

__global__ void __launch_bounds__(NB, 1)
schnet_main(const int*   __restrict__ Z,   const float* __restrict__ pos,
            const float* __restrict__ emb,
            const float* __restrict__ bo1, const float* __restrict__ bo2,
            const float* __restrict__ Wh1, const float* __restrict__ bh1,
            const float* __restrict__ Wh2, const float* __restrict__ bh2,
            float* __restrict__ out)
{
    extern __shared__ __align__(1024) char smc[];
    float* Xs    = (float*)(smc + SB_X);
    float* XFs   = (float*)(smc + SB_XF);
    float* BO1s  = (float*)(smc + SB_BO1);
    float* BO2s  = (float*)(smc + SB_BO2);
    float* POSs  = (float*)(smc + SB_POS);
    uint32_t* KOFFs = (uint32_t*)(smc + SB_KOFF);
    __half*  FRACHs = (__half*)(smc + SB_FRACH);
    uint32_t* A1H32 = (uint32_t*)(smc + SB_A1H);
    uint32_t* A1L32 = (uint32_t*)(smc + SB_A1L);
    uint32_t* A2H32 = (uint32_t*)(smc + SB_A2H);
    uint32_t* A2L32 = (uint32_t*)(smc + SB_A2L);
    unsigned short* PAIRs = (unsigned short*)(smc + SB_PAIR);
    uint2* ENTs = (uint2*)(smc + SB_ENT);
    const uint32_t smb = smem_u32(smc);

    const int tid = threadIdx.x, lane = tid & 31, w = tid >> 5;  // 32 warps
    const int blk = blockIdx.x;                  // molecule pair
    const int c4 = lane << 2;
    const int mr = (w & 3) * 16, nc = (w >> 2) * 16;   // 4 x 8 tile grid

    // ---------- init ----------
    if (tid < 2 * NA * 3) POSs[tid] = pos[blk * 2 * NA * 3 + tid];
    if (tid < 512) {
        int p = tid;
        unsigned short pr = 0;
        if (p < NP) {
            int i = 0, base = 0;
            while (p >= base + (31 - i)) { base += 31 - i; i++; }
            int j = i + 1 + (p - base);
            pr = (unsigned short)((i << 5) | j);
        }
        PAIRs[tid] = pr;
    }
    for (int idx = tid; idx < 2 * NA * DD; idx += NB) {
        int a = idx >> 7, cc = idx & (DD - 1);
        Xs[idx] = emb[Z[blk * 2 * NA + a] * DD + cc];
    }
    __syncthreads();
    for (int idx = tid; idx < 1024; idx += NB) {
        int m = idx >> 9, p = idx & 511;
        uint32_t ko = 0;
        __half fh = __float2half(0.f);
        if (p < NP) {
            int pr = PAIRs[p]; int i = pr >> 5, j = pr & 31;
            const float* pm = POSs + m * NA * 3;
            float dx = pm[i*3+0] - pm[j*3+0];
            float dy = pm[i*3+1] - pm[j*3+1];
            float dz = pm[i*3+2] - pm[j*3+2];
            float d = sqrtf(dx*dx + dy*dy + dz*dz);
            float t = fminf(d * KSCALE, (float)(TKNOTS - 1));
            int kf = min((int)t, TKNOTS - 2);
            ko = (uint32_t)kf * 512u;            // byte offset of paired entry
            fh = __float2half(t - (float)kf);
        }
        KOFFs[idx] = ko;
        FRACHs[idx] = fh;
    }
    __syncthreads();
    // fused entry table: ENT[m][a][e] = {koff, frach | other<<16}
    for (int idx = tid; idx < 1984; idx += NB) {
        int m = (idx >= 992) ? 1 : 0;
        int rem = idx - m * 992;
        int a = rem / 31, e = rem - a * 31;
        int p, other;
        if (e < a) { int i = e; p = i * 31 - (i * (i - 1)) / 2 + (a - i - 1); other = i; }
        else       { int j = e + 1; p = a * 31 - (a * (a - 1)) / 2 + (j - a - 1); other = j; }
        uint2 v;
        v.x = KOFFs[m * 512 + p];
        v.y = (uint32_t)__half_as_ushort(FRACHs[m * 512 + p]) | ((uint32_t)other << 16);
        ENTs[idx] = v;
    }
    __syncthreads();

    // ---------- layers ----------
    const uint2* gh = (const uint2*)g_wh;
    const uint2* gl = (const uint2*)g_wl;
    for (int l = 0; l < NLAY; l++) {
        // phase 1: stage Wi -> WB; split X -> A1 (64 rows); biases
        {
            const int wbI = l * 4096;
            for (int idx = tid; idx < 4096; idx += NB) {
                int row = idx >> 5, n4 = idx & 31;
                *(uint2*)(smc + SB_WBH + row * BSTR + n4 * 8) = gh[wbI + idx];
                *(uint2*)(smc + SB_WBL + row * BSTR + n4 * 8) = gl[wbI + idx];
            }
            for (int idx = tid; idx < 4096; idx += NB) {
                int row = idx >> 6, n2 = idx & 63;
                float2 v = *(const float2*)(Xs + row * DD + n2 * 2);
                uint32_t h0, l0, h1, l1;
                split2(v.x, h0, l0); split2(v.y, h1, l1);
                A1H32[row * 68 + n2] = h0 | (h1 << 16);
                A1L32[row * 68 + n2] = l0 | (l1 << 16);
            }
            if (tid < DD) {
                BO1s[tid] = bo1[l * DD + tid];
                BO2s[tid] = bo2[l * DD + tid];
            }
        }
        __syncthreads();
        // phase 2: in2f HMMA (64x128) -> XF
        {
            float c[2][4] = {{0,0,0,0},{0,0,0,0}};
            gemm16<8>(smb + SB_A1H, smb + SB_A1L, smb + SB_WBH, smb + SB_WBL,
                      mr, nc, lane, c);
            int r0 = mr + (lane >> 2);
            int cb = nc + (lane & 3) * 2;
            *(float2*)(XFs + r0 * DD + cb)           = make_float2(c[0][0], c[0][1]);
            *(float2*)(XFs + (r0 + 8) * DD + cb)     = make_float2(c[0][2], c[0][3]);
            *(float2*)(XFs + r0 * DD + cb + 8)       = make_float2(c[1][0], c[1][1]);
            *(float2*)(XFs + (r0 + 8) * DD + cb + 8) = make_float2(c[1][2], c[1][3]);
        }
        __syncthreads();   // XF ready; WB (Wi) dead

        // phase 3: stage Wo1 -> WB (hidden), msg loop (2 atoms/warp), dump agg
        {
            const int wb1 = (NLAY + l) * 4096;
            for (int idx = tid; idx < 4096; idx += NB) {
                int row = idx >> 5, n4 = idx & 31;
                *(uint2*)(smc + SB_WBH + row * BSTR + n4 * 8) = gh[wb1 + idx];
                *(uint2*)(smc + SB_WBL + row * BSTR + n4 * 8) = gl[wb1 + idx];
            }
        }
        {
            const char* tabB = (const char*)g_tab + (size_t)l * TKNOTS * 512;
            const uint2* entA = ENTs + w * 31;
            const uint2* entB = ENTs + 992 + w * 31;
            const int lb = lane * 16;
            float4 acA = {0,0,0,0}, acB = {0,0,0,0};
            #pragma unroll 2
            for (int e = 0; e < 31; e++) {
                uint2 eA = entA[e];
                uint2 eB = entB[e];
                {
                    uint4 ab = *(const uint4*)(tabB + eA.x + lb);
                    __half2 f2 = __half2half2(__ushort_as_half((unsigned short)(eA.y & 0xffff)));
                    float4 wv = lerp_p4(ab, f2);
                    int o = (int)(eA.y >> 16);
                    fma4v(acA, wv, *(const float4*)(XFs + o * DD + c4));
                }
                {
                    uint4 ab = *(const uint4*)(tabB + eB.x + lb);
                    __half2 f2 = __half2half2(__ushort_as_half((unsigned short)(eB.y & 0xffff)));
                    float4 wv = lerp_p4(ab, f2);
                    int o = (int)(eB.y >> 16);
                    fma4v(acB, wv, *(const float4*)(XFs + (NA + o) * DD + c4));
                }
            }
            float4* accs[2] = {&acA, &acB};
            int rows[2] = {w, NA + w};
            #pragma unroll
            for (int q = 0; q < 2; q++) {
                uint32_t h0,l0,h1,l1,h2,l2,h3,l3;
                split2(accs[q]->x, h0, l0); split2(accs[q]->y, h1, l1);
                split2(accs[q]->z, h2, l2); split2(accs[q]->w, h3, l3);
                A1H32[rows[q] * 68 + lane * 2]     = h0 | (h1 << 16);
                A1H32[rows[q] * 68 + lane * 2 + 1] = h2 | (h3 << 16);
                A1L32[rows[q] * 68 + lane * 2]     = l0 | (l1 << 16);
                A1L32[rows[q] * 68 + lane * 2 + 1] = l2 | (l3 << 16);
            }
        }
        __syncthreads();   // A1 ready; Wo1 staged
        // phase 4: f2out1: t1 = ssp(agg @ Wo1 + bo1) -> split -> A2
        {
            float c[2][4] = {{0,0,0,0},{0,0,0,0}};
            gemm16<8>(smb + SB_A1H, smb + SB_A1L, smb + SB_WBH, smb + SB_WBL,
                      mr, nc, lane, c);
            int r0 = mr + (lane >> 2);
            #pragma unroll
            for (int ni = 0; ni < 2; ni++)
                #pragma unroll
                for (int h = 0; h < 2; h++) {
                    int row = r0 + h * 8;
                    int col = nc + ni * 8 + (lane & 3) * 2;
                    float v0 = sspf(c[ni][h*2+0] + BO1s[col]);
                    float v1 = sspf(c[ni][h*2+1] + BO1s[col+1]);
                    uint32_t h0,l0,h1,l1;
                    split2(v0, h0, l0); split2(v1, h1, l1);
                    A2H32[row * 68 + (col >> 1)] = h0 | (h1 << 16);
                    A2L32[row * 68 + (col >> 1)] = l0 | (l1 << 16);
                }
        }
        __syncthreads();
        // phase 5: stage Wo2 -> WB (exposed)
        {
            const int wb2 = (2 * NLAY + l) * 4096;
            for (int idx = tid; idx < 4096; idx += NB) {
                int row = idx >> 5, n4 = idx & 31;
                *(uint2*)(smc + SB_WBH + row * BSTR + n4 * 8) = gh[wb2 + idx];
                *(uint2*)(smc + SB_WBL + row * BSTR + n4 * 8) = gl[wb2 + idx];
            }
        }
        __syncthreads();
        // phase 6: f2out2 + residual: x += t1 @ Wo2 + bo2
        {
            float c[2][4] = {{0,0,0,0},{0,0,0,0}};
            gemm16<8>(smb + SB_A2H, smb + SB_A2L, smb + SB_WBH, smb + SB_WBL,
                      mr, nc, lane, c);
            int r0 = mr + (lane >> 2);
            #pragma unroll
            for (int ni = 0; ni < 2; ni++)
                #pragma unroll
                for (int h = 0; h < 2; h++) {
                    int row = r0 + h * 8;
                    int col = nc + ni * 8 + (lane & 3) * 2;
                    float2 x = *(const float2*)(Xs + row * DD + col);
                    x.x += c[ni][h*2+0] + BO2s[col];
                    x.y += c[ni][h*2+1] + BO2s[col+1];
                    *(float2*)(Xs + row * DD + col) = x;
                }
        }
        __syncthreads();
    }

    // ---------- readout head (scratch in XF region), 2 molecules ----------
    float* HD = XFs;
    if (tid < 256) {
        int m = tid >> 7, cc = tid & 127;
        float s = 0.f;
        #pragma unroll
        for (int i = 0; i < NA; i++) s += Xs[(m * NA + i) * DD + cc];
        HD[tid] = s;
    }
    __syncthreads();
    if (tid < 256) {
        int m = tid >> 7, cc = tid & 127;
        float acc = 0.f;
        #pragma unroll 8
        for (int k = 0; k < DD; k++) acc = fmaf(HD[m * DD + k], Wh1[k * DD + cc], acc);
        float hpre = acc + bh1[cc];
        float h = hpre / (1.f + __expf(-hpre));
        HD[256 + tid] = h * Wh2[cc];
    }
    __syncthreads();
    if (tid < 2) {
        float s = bh2[0];
        #pragma unroll 8
        for (int k = 0; k < DD; k++) s += HD[256 + tid * DD + k];
        out[blk * 2 + tid] = s;
    }
}

extern "C" void kernel_launch(void* const* d_in, const int* in_sizes, int n_in,
                              void* d_out, int out_size)
{
    const int*   Z   = (const int*)  d_in[0];
    const float* pos = (const float*)d_in[1];
    const float* emb = (const float*)d_in[6];
    const float* Wi  = (const float*)d_in[7];
    const float* Wf1 = (const float*)d_in[8];
    const float* bf1 = (const float*)d_in[9];
    const float* Wf2 = (const float*)d_in[10];
    const float* bf2 = (const float*)d_in[11];
    const float* Wo1 = (const float*)d_in[12];
    const float* bo1 = (const float*)d_in[13];
    const float* Wo2 = (const float*)d_in[14];
    const float* bo2 = (const float*)d_in[15];
    const float* Wh1 = (const float*)d_in[16];
    const float* bh1 = (const float*)d_in[17];
    const float* Wh2 = (const float*)d_in[18];
    const float* bh2 = (const float*)d_in[19];

    const int B = out_size;
    const int smemA = A_FLOATS * sizeof(float);
    cudaFuncSetAttribute(build_table,
                         cudaFuncAttributeMaxDynamicSharedMemorySize, smemA);
    cudaFuncSetAttribute(schnet_main,
                         cudaFuncAttributeMaxDynamicSharedMemorySize, SMEM_BYTES);

    build_table<<<dim3(TKNOTS / 64, NLAY), 256, smemA>>>(Wf1, bf1, Wf2, bf2);
    build_wsplit<<<(3 * NLAY * DD * (DD / 2) + 1023) / 1024, 1024>>>(Wi, Wo1, Wo2);
    schnet_main<<<B / 2, NB, SMEM_BYTES>>>(Z, pos, emb, bo1, bo2,
                                           Wh1, bh1, Wh2, bh2, (float*)d_out);
}

// round 15
// speedup vs baseline: 1.0298x; 1.0298x over previous
#include <cuda_runtime.h>
#include <cuda_bf16.h>
#include <cuda_fp16.h>
#include <cstdint>

#define NB 512
constexpr int NA = 32;
constexpr int DD = 128;
constexpr int RR = 50;
constexpr int NP = 496;
constexpr int NLAY = 6;
constexpr int TKNOTS = 2048;
constexpr float CUTOFF = 5.0f;
constexpr float WIDTH  = CUTOFF / (RR - 1);
constexpr float COEFF  = -0.5f / (WIDTH * WIDTH);
constexpr float LN2    = 0.69314718055994531f;
constexpr float PIF    = 3.14159265358979323846f;
constexpr float HSTEP  = CUTOFF / (TKNOTS - 1);
constexpr float KSCALE = (TKNOTS - 1) / CUTOFF;
constexpr int BSTR = 272;    // bf16 operand row stride (bytes) = 136 halves

// ---------------- device globals ----------------
// paired filter table: entry k holds (W_k, W_{k+1}) interleaved per 4-ch group.
// entry = 512 B: per lane (4 ch): uint4 { a01, a23, b01, b23 } at lane*16.
__device__ __half   g_tab[(size_t)NLAY * TKNOTS * 256];
__device__ uint32_t g_wh[3 * NLAY * DD * (DD / 2)];               // bf16-hi packed pairs
__device__ uint32_t g_wl[3 * NLAY * DD * (DD / 2)];               // bf16-lo packed pairs

// ---------------- helpers ----------------
__device__ __forceinline__ uint32_t smem_u32(const void* p) {
    uint32_t a;
    asm("{ .reg .u64 t; cvta.to.shared.u64 t, %1; cvt.u32.u64 %0, t; }"
        : "=r"(a) : "l"(p));
    return a;
}
__device__ __forceinline__ void ldsm4(uint32_t* r, uint32_t a) {
    asm volatile("ldmatrix.sync.aligned.m8n8.x4.shared.b16 {%0,%1,%2,%3}, [%4];"
        : "=r"(r[0]), "=r"(r[1]), "=r"(r[2]), "=r"(r[3]) : "r"(a));
}
__device__ __forceinline__ void ldsm4t(uint32_t* r, uint32_t a) {
    asm volatile("ldmatrix.sync.aligned.m8n8.x4.trans.shared.b16 {%0,%1,%2,%3}, [%4];"
        : "=r"(r[0]), "=r"(r[1]), "=r"(r[2]), "=r"(r[3]) : "r"(a));
}
__device__ __forceinline__ void mmabf(float* c, const uint32_t* a, const uint32_t* b) {
    asm volatile("mma.sync.aligned.m16n8k16.row.col.f32.bf16.bf16.f32 "
        "{%0,%1,%2,%3}, {%4,%5,%6,%7}, {%8,%9}, {%0,%1,%2,%3};"
        : "+f"(c[0]), "+f"(c[1]), "+f"(c[2]), "+f"(c[3])
        : "r"(a[0]), "r"(a[1]), "r"(a[2]), "r"(a[3]), "r"(b[0]), "r"(b[1]));
}
__device__ __forceinline__ void split2(float x, uint32_t& h, uint32_t& l) {
    __nv_bfloat16 hb = __float2bfloat16(x);
    __nv_bfloat16 lb = __float2bfloat16(x - __bfloat162float(hb));
    h = (uint32_t)__bfloat16_as_ushort(hb);
    l = (uint32_t)__bfloat16_as_ushort(lb);
}
__device__ __forceinline__ float sspf(float x) {
    float r = __logf(fmaf(0.5f, __expf(x), 0.5f));
    return (x > 20.f) ? x - LN2 : r;
}
__device__ __forceinline__ void fma4(float4& a, float s, const float4& b) {
    a.x = fmaf(s, b.x, a.x); a.y = fmaf(s, b.y, a.y);
    a.z = fmaf(s, b.z, a.z); a.w = fmaf(s, b.w, a.w);
}
__device__ __forceinline__ void fma4v(float4& a, const float4& s, const float4& b) {
    a.x = fmaf(s.x, b.x, a.x); a.y = fmaf(s.y, b.y, a.y);
    a.z = fmaf(s.z, b.z, a.z); a.w = fmaf(s.w, b.w, a.w);
}
__device__ __forceinline__ float comp(const float4& v, int k) { return ((const float*)&v)[k]; }

// lerp paired entry (a01,a23,b01,b23) with half2 arithmetic -> fp32x4
__device__ __forceinline__ float4 lerp_p4(uint4 ab, __half2 f2) {
    __half2 a0 = *reinterpret_cast<__half2*>(&ab.x);
    __half2 a1 = *reinterpret_cast<__half2*>(&ab.y);
    __half2 b0 = *reinterpret_cast<__half2*>(&ab.z);
    __half2 b1 = *reinterpret_cast<__half2*>(&ab.w);
    __half2 w0 = __hfma2(f2, __hsub2(b0, a0), a0);
    __half2 w1 = __hfma2(f2, __hsub2(b1, a1), a1);
    float2 lo = __half22float2(w0), hi = __half22float2(w1);
    return make_float4(lo.x, lo.y, hi.x, hi.y);
}

// 16x16 output warp tile, K=16*KS, 3-pass split-bf16. A[m][k] stride BSTR, B[k][n] stride BSTR.
template<int KS>
__device__ __forceinline__ void gemm16(
    uint32_t aH, uint32_t aL, uint32_t bH, uint32_t bL,
    int mr, int nc, int lane, float (*c)[4])
{
    const uint32_t aoff = (uint32_t)((mr + (lane & 7) + ((lane >> 3) & 1) * 8) * BSTR
                                     + ((lane >> 4) & 1) * 16);
    const uint32_t boff = (uint32_t)(((lane & 7) + ((lane >> 3) & 1) * 8) * BSTR
                                     + (nc + ((lane >> 4) & 1) * 8) * 2);
    #pragma unroll
    for (int ks = 0; ks < KS; ks++) {
        const uint32_t ao = aoff + ks * 32;
        const uint32_t bo = boff + ks * 16 * BSTR;
        uint32_t Ah[4], Al[4], Bh[4], Bl[4];
        ldsm4(Ah, aH + ao);
        ldsm4t(Bh, bH + bo);
        mmabf(c[0], Ah, Bh); mmabf(c[1], Ah, Bh + 2);
        ldsm4t(Bl, bL + bo);
        mmabf(c[0], Ah, Bl); mmabf(c[1], Ah, Bl + 2);
        ldsm4(Al, aL + ao);
        mmabf(c[0], Al, Bh); mmabf(c[1], Al, Bh + 2);
    }
}

// ======= builder 1 (256 thr, 64 knots/CTA, 8 rows/warp), paired output ==========
constexpr int A_W1 = 0;          // 52x128
constexpr int A_W2 = 6656;       // 128x128
constexpr int A_F  = 23040;      // 64x52
constexpr int A_H1 = 26368;      // 64x128
constexpr int A_B1 = 34560;
constexpr int A_B2 = 34688;
constexpr int A_FLOATS = 34816;

__global__ void __launch_bounds__(256, 1)
build_table(const float* __restrict__ Wf1, const float* __restrict__ bf1,
            const float* __restrict__ Wf2, const float* __restrict__ bf2)
{
    extern __shared__ float sa[];
    const int tid = threadIdx.x, lane = tid & 31, w = tid >> 5;   // 8 warps
    const int layer = blockIdx.y;
    const int kb = blockIdx.x * 64;
    const int c4 = lane << 2;

    for (int idx = tid; idx < 52 * 128; idx += 256) {
        int k = idx >> 7, n = idx & 127;
        sa[A_W1 + idx] = (k < RR) ? Wf1[layer * RR * DD + k * DD + n] : 0.f;
    }
    for (int idx = tid; idx < 128 * 128; idx += 256)
        sa[A_W2 + idx] = Wf2[layer * DD * DD + idx];
    if (tid < 128) {
        sa[A_B1 + tid] = bf1[layer * DD + tid];
        sa[A_B2 + tid] = bf2[layer * DD + tid];
    }
    for (int idx = tid; idx < 64 * 52; idx += 256) {
        int row = idx / 52, r = idx - row * 52;
        float d = (float)(kb + row) * HSTEP;
        float t = d - (float)r * WIDTH;
        sa[A_F + idx] = (r < RR) ? __expf(COEFF * t * t) : 0.f;
    }
    __syncthreads();

    for (int blk = 0; blk < 2; blk++) {
        const int r0 = w * 8 + blk * 4;
        float4 ac0 = {0,0,0,0}, ac1 = {0,0,0,0}, ac2 = {0,0,0,0}, ac3 = {0,0,0,0};
        #pragma unroll
        for (int k = 0; k < 52; k += 4) {
            float4 a0 = *(const float4*)(sa + A_F + (r0 + 0) * 52 + k);
            float4 a1 = *(const float4*)(sa + A_F + (r0 + 1) * 52 + k);
            float4 a2 = *(const float4*)(sa + A_F + (r0 + 2) * 52 + k);
            float4 a3 = *(const float4*)(sa + A_F + (r0 + 3) * 52 + k);
            #pragma unroll
            for (int kk = 0; kk < 4; kk++) {
                float4 b = *(const float4*)(sa + A_W1 + (k + kk) * 128 + c4);
                fma4(ac0, comp(a0, kk), b); fma4(ac1, comp(a1, kk), b);
                fma4(ac2, comp(a2, kk), b); fma4(ac3, comp(a3, kk), b);
            }
        }
        float4 bb = *(const float4*)(sa + A_B1 + c4);
        float4* accs[4] = {&ac0, &ac1, &ac2, &ac3};
        #pragma unroll
        for (int m = 0; m < 4; m++) {
            float4 o;
            o.x = sspf(accs[m]->x + bb.x); o.y = sspf(accs[m]->y + bb.y);
            o.z = sspf(accs[m]->z + bb.z); o.w = sspf(accs[m]->w + bb.w);
            *(float4*)(sa + A_H1 + (r0 + m) * 128 + c4) = o;
        }
    }
    __syncthreads();

    char* gt = (char*)g_tab;
    for (int blk = 0; blk < 2; blk++) {
        const int r0 = w * 8 + blk * 4;
        float4 ac0 = {0,0,0,0}, ac1 = {0,0,0,0}, ac2 = {0,0,0,0}, ac3 = {0,0,0,0};
        #pragma unroll 4
        for (int k = 0; k < 128; k += 4) {
            float4 a0 = *(const float4*)(sa + A_H1 + (r0 + 0) * 128 + k);
            float4 a1 = *(const float4*)(sa + A_H1 + (r0 + 1) * 128 + k);
            float4 a2 = *(const float4*)(sa + A_H1 + (r0 + 2) * 128 + k);
            float4 a3 = *(const float4*)(sa + A_H1 + (r0 + 3) * 128 + k);
            #pragma unroll
            for (int kk = 0; kk < 4; kk++) {
                float4 b = *(const float4*)(sa + A_W2 + (k + kk) * 128 + c4);
                fma4(ac0, comp(a0, kk), b); fma4(ac1, comp(a1, kk), b);
                fma4(ac2, comp(a2, kk), b); fma4(ac3, comp(a3, kk), b);
            }
        }
        float4 bb = *(const float4*)(sa + A_B2 + c4);
        float4* accs[4] = {&ac0, &ac1, &ac2, &ac3};
        #pragma unroll
        for (int m = 0; m < 4; m++) {
            int rowg = kb + r0 + m;
            float d = (float)rowg * HSTEP;
            float rc = (d < CUTOFF) ? 0.5f * (__cosf(d * (PIF / CUTOFF)) + 1.f) : 0.f;
            float4 o;
            o.x = (accs[m]->x + bb.x) * rc; o.y = (accs[m]->y + bb.y) * rc;
            o.z = (accs[m]->z + bb.z) * rc; o.w = (accs[m]->w + bb.w) * rc;
            __half h0 = __float2half_rn(o.x), h1 = __float2half_rn(o.y);
            __half h2 = __float2half_rn(o.z), h3 = __float2half_rn(o.w);
            uint2 pk;
            pk.x = (uint32_t)__half_as_ushort(h0) | ((uint32_t)__half_as_ushort(h1) << 16);
            pk.y = (uint32_t)__half_as_ushort(h2) | ((uint32_t)__half_as_ushort(h3) << 16);
            size_t eb = ((size_t)layer * TKNOTS + rowg) * 512;
            *(uint2*)(gt + eb + lane * 16) = pk;                   // a-slot of entry rowg
            if (rowg > 0)
                *(uint2*)(gt + eb - 512 + lane * 16 + 8) = pk;     // b-slot of entry rowg-1
        }
    }
}

// ================= builder 2: split Wi/Wo1/Wo2 to bf16 hi/lo =================
__global__ void __launch_bounds__(1024, 1)
build_wsplit(const float* __restrict__ Wi,
             const float* __restrict__ Wo1,
             const float* __restrict__ Wo2)
{
    int idx = blockIdx.x * 1024 + threadIdx.x;
    const int TOT = 3 * NLAY * DD * (DD / 2);
    if (idx >= TOT) return;
    int mat = idx / (NLAY * DD * (DD / 2));
    int rem = idx - mat * (NLAY * DD * (DD / 2));
    const float* src = (mat == 0) ? Wi : (mat == 1) ? Wo1 : Wo2;
    float v0 = src[rem * 2];
    float v1 = src[rem * 2 + 1];
    uint32_t h0, l0, h1, l1;
    split2(v0, h0, l0); split2(v1, h1, l1);
    g_wh[idx] = h0 | (h1 << 16);
    g_wl[idx] = l0 | (l1 << 16);
}

// ================= main kernel: 2 molecules / CTA =================
constexpr int SB_WBH  = 0;         // 128 x 272B = 34816  (Wi -> Wo1 -> Wo2)
constexpr int SB_WBL  = 34816;     // -> 69632
constexpr int SB_X    = 69632;     // 64x128 f32 = 32768 -> 102400
constexpr int SB_XF   = 102400;    // 32768 -> 135168 (head scratch later)
constexpr int SB_A1H  = 135168;    // 64 x 272B = 17408 -> 152576
constexpr int SB_A1L  = 152576;    // -> 169984
constexpr int SB_A2H  = 169984;    // -> 187392
constexpr int SB_A2L  = 187392;    // -> 204800
constexpr int SB_BO1  = 204800;    // 128 f32 -> 205312
constexpr int SB_BO2  = 205312;    // -> 205824
constexpr int SB_POS  = 205824;    // 192 f32 (pad 1024) -> 206848
constexpr int SB_KOFF = 206848;    // 1024 u32 -> 210944
constexpr int SB_FRACH= 210944;    // 1024 f16 -> 212992
constexpr int SB_PAIR = 212992;    // 512 u16 -> 214016
constexpr int SB_ENT  = 214016;    // 2 x 32 x 31 x 8B = 15872 -> 229888
constexpr int SMEM_BYTES = 229888;

__global__ void __launch_bounds__(NB, 1)
schnet_main(const int*   __restrict__ Z,   const float* __restrict__ pos,
            const float* __restrict__ emb,
            const float* __restrict__ bo1, const float* __restrict__ bo2,
            const float* __restrict__ Wh1, const float* __restrict__ bh1,
            const float* __restrict__ Wh2, const float* __restrict__ bh2,
            float* __restrict__ out)
{
    extern __shared__ __align__(1024) char smc[];
    float* Xs    = (float*)(smc + SB_X);
    float* XFs   = (float*)(smc + SB_XF);
    float* BO1s  = (float*)(smc + SB_BO1);
    float* BO2s  = (float*)(smc + SB_BO2);
    float* POSs  = (float*)(smc + SB_POS);
    uint32_t* KOFFs = (uint32_t*)(smc + SB_KOFF);
    __half*  FRACHs = (__half*)(smc + SB_FRACH);
    uint32_t* A1H32 = (uint32_t*)(smc + SB_A1H);
    uint32_t* A1L32 = (uint32_t*)(smc + SB_A1L);
    uint32_t* A2H32 = (uint32_t*)(smc + SB_A2H);
    uint32_t* A2L32 = (uint32_t*)(smc + SB_A2L);
    unsigned short* PAIRs = (unsigned short*)(smc + SB_PAIR);
    uint2* ENTs = (uint2*)(smc + SB_ENT);
    const uint32_t smb = smem_u32(smc);

    const int tid = threadIdx.x, lane = tid & 31, w = tid >> 5;
    const int blk = blockIdx.x;                  // molecule pair
    const int c4 = lane << 2;
    const int mr = (w & 3) * 16, nc0 = (w >> 2) * 32;   // HMMA: 64-row A, 2 col tiles

    // ---------- init ----------
    if (tid < 2 * NA * 3) POSs[tid] = pos[blk * 2 * NA * 3 + tid];
    {
        int p = tid;
        unsigned short pr = 0;
        if (p < NP) {
            int i = 0, base = 0;
            while (p >= base + (31 - i)) { base += 31 - i; i++; }
            int j = i + 1 + (p - base);
            pr = (unsigned short)((i << 5) | j);
        }
        if (tid < 512) PAIRs[tid] = pr;
    }
    for (int idx = tid; idx < 2 * NA * DD; idx += NB) {
        int a = idx >> 7, cc = idx & (DD - 1);
        Xs[idx] = emb[Z[blk * 2 * NA + a] * DD + cc];
    }
    __syncthreads();
    for (int idx = tid; idx < 1024; idx += NB) {
        int m = idx >> 9, p = idx & 511;
        uint32_t ko = 0;
        __half fh = __float2half(0.f);
        if (p < NP) {
            int pr = PAIRs[p]; int i = pr >> 5, j = pr & 31;
            const float* pm = POSs + m * NA * 3;
            float dx = pm[i*3+0] - pm[j*3+0];
            float dy = pm[i*3+1] - pm[j*3+1];
            float dz = pm[i*3+2] - pm[j*3+2];
            float d = sqrtf(dx*dx + dy*dy + dz*dz);
            float t = fminf(d * KSCALE, (float)(TKNOTS - 1));
            int kf = min((int)t, TKNOTS - 2);
            ko = (uint32_t)kf * 512u;            // byte offset of paired entry
            fh = __float2half(t - (float)kf);
        }
        KOFFs[idx] = ko;
        FRACHs[idx] = fh;
    }
    __syncthreads();
    // fused entry table: ENT[m][a][e] = {koff, frach | other<<16}
    for (int idx = tid; idx < 1984; idx += NB) {
        int m = (idx >= 992) ? 1 : 0;
        int rem = idx - m * 992;
        int a = rem / 31, e = rem - a * 31;
        int p, other;
        if (e < a) { int i = e; p = i * 31 - (i * (i - 1)) / 2 + (a - i - 1); other = i; }
        else       { int j = e + 1; p = a * 31 - (a * (a - 1)) / 2 + (j - a - 1); other = j; }
        uint2 v;
        v.x = KOFFs[m * 512 + p];
        v.y = (uint32_t)__half_as_ushort(FRACHs[m * 512 + p]) | ((uint32_t)other << 16);
        ENTs[idx] = v;
    }
    __syncthreads();

    // ---------- layers ----------
    const uint2* gh = (const uint2*)g_wh;
    const uint2* gl = (const uint2*)g_wl;
    for (int l = 0; l < NLAY; l++) {
        // phase 1: stage Wi -> WB; split X -> A1 (64 rows); biases
        {
            const int wbI = l * 4096;
            for (int idx = tid; idx < 4096; idx += NB) {
                int row = idx >> 5, n4 = idx & 31;
                *(uint2*)(smc + SB_WBH + row * BSTR + n4 * 8) = gh[wbI + idx];
                *(uint2*)(smc + SB_WBL + row * BSTR + n4 * 8) = gl[wbI + idx];
            }
            for (int idx = tid; idx < 4096; idx += NB) {
                int row = idx >> 6, n2 = idx & 63;
                float2 v = *(const float2*)(Xs + row * DD + n2 * 2);
                uint32_t h0, l0, h1, l1;
                split2(v.x, h0, l0); split2(v.y, h1, l1);
                A1H32[row * 68 + n2] = h0 | (h1 << 16);
                A1L32[row * 68 + n2] = l0 | (l1 << 16);
            }
            if (tid < DD) {
                BO1s[tid] = bo1[l * DD + tid];
                BO2s[tid] = bo2[l * DD + tid];
            }
        }
        __syncthreads();
        // phase 2: in2f HMMA (64x128) -> XF
        {
            float c[2][2][4] = {{{0,0,0,0},{0,0,0,0}},{{0,0,0,0},{0,0,0,0}}};
            gemm16<8>(smb + SB_A1H, smb + SB_A1L, smb + SB_WBH, smb + SB_WBL,
                      mr, nc0, lane, c[0]);
            gemm16<8>(smb + SB_A1H, smb + SB_A1L, smb + SB_WBH, smb + SB_WBL,
                      mr, nc0 + 16, lane, c[1]);
            int r0 = mr + (lane >> 2);
            #pragma unroll
            for (int tI = 0; tI < 2; tI++) {
                int cb = nc0 + tI * 16 + (lane & 3) * 2;
                *(float2*)(XFs + r0 * DD + cb)           = make_float2(c[tI][0][0], c[tI][0][1]);
                *(float2*)(XFs + (r0 + 8) * DD + cb)     = make_float2(c[tI][0][2], c[tI][0][3]);
                *(float2*)(XFs + r0 * DD + cb + 8)       = make_float2(c[tI][1][0], c[tI][1][1]);
                *(float2*)(XFs + (r0 + 8) * DD + cb + 8) = make_float2(c[tI][1][2], c[tI][1][3]);
            }
        }
        __syncthreads();   // XF ready; WB (Wi) dead

        // phase 3: stage Wo1 -> WB (hidden), msg loop (4 atoms/warp), dump agg
        {
            const int wb1 = (NLAY + l) * 4096;
            for (int idx = tid; idx < 4096; idx += NB) {
                int row = idx >> 5, n4 = idx & 31;
                *(uint2*)(smc + SB_WBH + row * BSTR + n4 * 8) = gh[wb1 + idx];
                *(uint2*)(smc + SB_WBL + row * BSTR + n4 * 8) = gl[wb1 + idx];
            }
        }
        {
            const char* tabB = (const char*)g_tab + (size_t)l * TKNOTS * 512;
            const uint2* entA = ENTs;
            const uint2* entB = ENTs + 992;
            const int a0 = w, a1 = w + 16;
            const int lb = lane * 16;
            float4 acA0 = {0,0,0,0}, acA1 = {0,0,0,0};
            float4 acB0 = {0,0,0,0}, acB1 = {0,0,0,0};
            #pragma unroll 2
            for (int e = 0; e < 31; e++) {
                uint2 eA0 = entA[a0 * 31 + e];
                uint2 eA1 = entA[a1 * 31 + e];
                uint2 eB0 = entB[a0 * 31 + e];
                uint2 eB1 = entB[a1 * 31 + e];
                {
                    uint4 ab = *(const uint4*)(tabB + eA0.x + lb);
                    __half2 f2 = __half2half2(__ushort_as_half((unsigned short)(eA0.y & 0xffff)));
                    float4 wv = lerp_p4(ab, f2);
                    int o = (int)(eA0.y >> 16);
                    fma4v(acA0, wv, *(const float4*)(XFs + o * DD + c4));
                }
                {
                    uint4 ab = *(const uint4*)(tabB + eA1.x + lb);
                    __half2 f2 = __half2half2(__ushort_as_half((unsigned short)(eA1.y & 0xffff)));
                    float4 wv = lerp_p4(ab, f2);
                    int o = (int)(eA1.y >> 16);
                    fma4v(acA1, wv, *(const float4*)(XFs + o * DD + c4));
                }
                {
                    uint4 ab = *(const uint4*)(tabB + eB0.x + lb);
                    __half2 f2 = __half2half2(__ushort_as_half((unsigned short)(eB0.y & 0xffff)));
                    float4 wv = lerp_p4(ab, f2);
                    int o = (int)(eB0.y >> 16);
                    fma4v(acB0, wv, *(const float4*)(XFs + (NA + o) * DD + c4));
                }
                {
                    uint4 ab = *(const uint4*)(tabB + eB1.x + lb);
                    __half2 f2 = __half2half2(__ushort_as_half((unsigned short)(eB1.y & 0xffff)));
                    float4 wv = lerp_p4(ab, f2);
                    int o = (int)(eB1.y >> 16);
                    fma4v(acB1, wv, *(const float4*)(XFs + (NA + o) * DD + c4));
                }
            }
            float4* accs[4] = {&acA0, &acA1, &acB0, &acB1};
            int rows[4] = {w, w + 16, NA + w, NA + 16 + w};
            #pragma unroll
            for (int q = 0; q < 4; q++) {
                uint32_t h0,l0,h1,l1,h2,l2,h3,l3;
                split2(accs[q]->x, h0, l0); split2(accs[q]->y, h1, l1);
                split2(accs[q]->z, h2, l2); split2(accs[q]->w, h3, l3);
                A1H32[rows[q] * 68 + lane * 2]     = h0 | (h1 << 16);
                A1H32[rows[q] * 68 + lane * 2 + 1] = h2 | (h3 << 16);
                A1L32[rows[q] * 68 + lane * 2]     = l0 | (l1 << 16);
                A1L32[rows[q] * 68 + lane * 2 + 1] = l2 | (l3 << 16);
            }
        }
        __syncthreads();   // A1 ready; Wo1 staged
        // phase 4: prefetch Wo2 to regs; f2out1: t1 = ssp(agg @ Wo1 + bo1) -> A2
        uint2 pfh[8], pfl[8];
        {
            const int wb2 = (2 * NLAY + l) * 4096;
            #pragma unroll
            for (int it = 0; it < 8; it++) {
                int idx = tid + it * NB;
                pfh[it] = gh[wb2 + idx];
                pfl[it] = gl[wb2 + idx];
            }
            float c[2][2][4] = {{{0,0,0,0},{0,0,0,0}},{{0,0,0,0},{0,0,0,0}}};
            gemm16<8>(smb + SB_A1H, smb + SB_A1L, smb + SB_WBH, smb + SB_WBL,
                      mr, nc0, lane, c[0]);
            gemm16<8>(smb + SB_A1H, smb + SB_A1L, smb + SB_WBH, smb + SB_WBL,
                      mr, nc0 + 16, lane, c[1]);
            int r0 = mr + (lane >> 2);
            #pragma unroll
            for (int tI = 0; tI < 2; tI++)
                #pragma unroll
                for (int ni = 0; ni < 2; ni++)
                    #pragma unroll
                    for (int h = 0; h < 2; h++) {
                        int row = r0 + h * 8;
                        int col = nc0 + tI * 16 + ni * 8 + (lane & 3) * 2;
                        float v0 = sspf(c[tI][ni][h*2+0] + BO1s[col]);
                        float v1 = sspf(c[tI][ni][h*2+1] + BO1s[col+1]);
                        uint32_t h0,l0,h1,l1;
                        split2(v0, h0, l0); split2(v1, h1, l1);
                        A2H32[row * 68 + (col >> 1)] = h0 | (h1 << 16);
                        A2L32[row * 68 + (col >> 1)] = l0 | (l1 << 16);
                    }
        }
        __syncthreads();
        // phase 5: store prefetched Wo2 -> WB (STS only)
        {
            #pragma unroll
            for (int it = 0; it < 8; it++) {
                int idx = tid + it * NB;
                int row = idx >> 5, n4 = idx & 31;
                *(uint2*)(smc + SB_WBH + row * BSTR + n4 * 8) = pfh[it];
                *(uint2*)(smc + SB_WBL + row * BSTR + n4 * 8) = pfl[it];
            }
        }
        __syncthreads();
        // phase 6: f2out2 + residual: x += t1 @ Wo2 + bo2
        {
            float c[2][2][4] = {{{0,0,0,0},{0,0,0,0}},{{0,0,0,0},{0,0,0,0}}};
            gemm16<8>(smb + SB_A2H, smb + SB_A2L, smb + SB_WBH, smb + SB_WBL,
                      mr, nc0, lane, c[0]);
            gemm16<8>(smb + SB_A2H, smb + SB_A2L, smb + SB_WBH, smb + SB_WBL,
                      mr, nc0 + 16, lane, c[1]);
            int r0 = mr + (lane >> 2);
            #pragma unroll
            for (int tI = 0; tI < 2; tI++)
                #pragma unroll
                for (int ni = 0; ni < 2; ni++)
                    #pragma unroll
                    for (int h = 0; h < 2; h++) {
                        int row = r0 + h * 8;
                        int col = nc0 + tI * 16 + ni * 8 + (lane & 3) * 2;
                        float2 x = *(const float2*)(Xs + row * DD + col);
                        x.x += c[tI][ni][h*2+0] + BO2s[col];
                        x.y += c[tI][ni][h*2+1] + BO2s[col+1];
                        *(float2*)(Xs + row * DD + col) = x;
                    }
        }
        __syncthreads();
    }

    // ---------- readout head (scratch in XF region), 2 molecules ----------
    float* HD = XFs;
    if (tid < 256) {
        int m = tid >> 7, cc = tid & 127;
        float s = 0.f;
        #pragma unroll
        for (int i = 0; i < NA; i++) s += Xs[(m * NA + i) * DD + cc];
        HD[tid] = s;
    }
    __syncthreads();
    if (tid < 256) {
        int m = tid >> 7, cc = tid & 127;
        float acc = 0.f;
        #pragma unroll 8
        for (int k = 0; k < DD; k++) acc = fmaf(HD[m * DD + k], Wh1[k * DD + cc], acc);
        float hpre = acc + bh1[cc];
        float h = hpre / (1.f + __expf(-hpre));
        HD[256 + tid] = h * Wh2[cc];
    }
    __syncthreads();
    if (tid < 2) {
        float s = bh2[0];
        #pragma unroll 8
        for (int k = 0; k < DD; k++) s += HD[256 + tid * DD + k];
        out[blk * 2 + tid] = s;
    }
}

extern "C" void kernel_launch(void* const* d_in, const int* in_sizes, int n_in,
                              void* d_out, int out_size)
{
    const int*   Z   = (const int*)  d_in[0];
    const float* pos = (const float*)d_in[1];
    const float* emb = (const float*)d_in[6];
    const float* Wi  = (const float*)d_in[7];
    const float* Wf1 = (const float*)d_in[8];
    const float* bf1 = (const float*)d_in[9];
    const float* Wf2 = (const float*)d_in[10];
    const float* bf2 = (const float*)d_in[11];
    const float* Wo1 = (const float*)d_in[12];
    const float* bo1 = (const float*)d_in[13];
    const float* Wo2 = (const float*)d_in[14];
    const float* bo2 = (const float*)d_in[15];
    const float* Wh1 = (const float*)d_in[16];
    const float* bh1 = (const float*)d_in[17];
    const float* Wh2 = (const float*)d_in[18];
    const float* bh2 = (const float*)d_in[19];

    const int B = out_size;
    const int smemA = A_FLOATS * sizeof(float);
    cudaFuncSetAttribute(build_table,
                         cudaFuncAttributeMaxDynamicSharedMemorySize, smemA);
    cudaFuncSetAttribute(schnet_main,
                         cudaFuncAttributeMaxDynamicSharedMemorySize, SMEM_BYTES);

    build_table<<<dim3(TKNOTS / 64, NLAY), 256, smemA>>>(Wf1, bf1, Wf2, bf2);
    build_wsplit<<<(3 * NLAY * DD * (DD / 2) + 1023) / 1024, 1024>>>(Wi, Wo1, Wo2);
    schnet_main<<<B / 2, NB, SMEM_BYTES>>>(Z, pos, emb, bo1, bo2,
                                           Wh1, bh1, Wh2, bh2, (float*)d_out);
}

// round 16
// speedup vs baseline: 1.1497x; 1.1164x over previous
#include <cuda_runtime.h>
#include <cuda_bf16.h>
#include <cuda_fp16.h>
#include <cstdint>

#define NB 512
constexpr int NA = 32;
constexpr int DD = 128;
constexpr int RR = 50;
constexpr int NP = 496;
constexpr int NLAY = 6;
constexpr int TKNOTS = 1024;
constexpr float CUTOFF = 5.0f;
constexpr float WIDTH  = CUTOFF / (RR - 1);
constexpr float COEFF  = -0.5f / (WIDTH * WIDTH);
constexpr float LN2    = 0.69314718055994531f;
constexpr float PIF    = 3.14159265358979323846f;
constexpr float HSTEP  = CUTOFF / (TKNOTS - 1);
constexpr float KSCALE = (TKNOTS - 1) / CUTOFF;
constexpr int BSTR = 272;    // bf16 operand row stride (bytes) = 136 halves

// ---------------- device globals ----------------
// paired filter table: entry k holds (W_k, W_{k+1}) interleaved per 4-ch group.
// entry = 512 B: per lane (4 ch): uint4 { a01, a23, b01, b23 } at lane*16.
__device__ __half   g_tab[(size_t)NLAY * TKNOTS * 256];
__device__ uint32_t g_wh[3 * NLAY * DD * (DD / 2)];               // bf16-hi packed pairs
__device__ uint32_t g_wl[3 * NLAY * DD * (DD / 2)];               // bf16-lo packed pairs

// ---------------- helpers ----------------
__device__ __forceinline__ uint32_t smem_u32(const void* p) {
    uint32_t a;
    asm("{ .reg .u64 t; cvta.to.shared.u64 t, %1; cvt.u32.u64 %0, t; }"
        : "=r"(a) : "l"(p));
    return a;
}
__device__ __forceinline__ void ldsm4(uint32_t* r, uint32_t a) {
    asm volatile("ldmatrix.sync.aligned.m8n8.x4.shared.b16 {%0,%1,%2,%3}, [%4];"
        : "=r"(r[0]), "=r"(r[1]), "=r"(r[2]), "=r"(r[3]) : "r"(a));
}
__device__ __forceinline__ void ldsm4t(uint32_t* r, uint32_t a) {
    asm volatile("ldmatrix.sync.aligned.m8n8.x4.trans.shared.b16 {%0,%1,%2,%3}, [%4];"
        : "=r"(r[0]), "=r"(r[1]), "=r"(r[2]), "=r"(r[3]) : "r"(a));
}
__device__ __forceinline__ void mmabf(float* c, const uint32_t* a, const uint32_t* b) {
    asm volatile("mma.sync.aligned.m16n8k16.row.col.f32.bf16.bf16.f32 "
        "{%0,%1,%2,%3}, {%4,%5,%6,%7}, {%8,%9}, {%0,%1,%2,%3};"
        : "+f"(c[0]), "+f"(c[1]), "+f"(c[2]), "+f"(c[3])
        : "r"(a[0]), "r"(a[1]), "r"(a[2]), "r"(a[3]), "r"(b[0]), "r"(b[1]));
}
__device__ __forceinline__ void split2(float x, uint32_t& h, uint32_t& l) {
    __nv_bfloat16 hb = __float2bfloat16(x);
    __nv_bfloat16 lb = __float2bfloat16(x - __bfloat162float(hb));
    h = (uint32_t)__bfloat16_as_ushort(hb);
    l = (uint32_t)__bfloat16_as_ushort(lb);
}
__device__ __forceinline__ uint32_t packbf2(float x, float y) {   // bf16(x) | bf16(y)<<16
    uint32_t hx = (uint32_t)__bfloat16_as_ushort(__float2bfloat16(x));
    uint32_t hy = (uint32_t)__bfloat16_as_ushort(__float2bfloat16(y));
    return hx | (hy << 16);
}
__device__ __forceinline__ float sspf(float x) {
    float r = __logf(fmaf(0.5f, __expf(x), 0.5f));
    return (x > 20.f) ? x - LN2 : r;
}
__device__ __forceinline__ void fma4(float4& a, float s, const float4& b) {
    a.x = fmaf(s, b.x, a.x); a.y = fmaf(s, b.y, a.y);
    a.z = fmaf(s, b.z, a.z); a.w = fmaf(s, b.w, a.w);
}
__device__ __forceinline__ void fma4v(float4& a, const float4& s, const float4& b) {
    a.x = fmaf(s.x, b.x, a.x); a.y = fmaf(s.y, b.y, a.y);
    a.z = fmaf(s.z, b.z, a.z); a.w = fmaf(s.w, b.w, a.w);
}
__device__ __forceinline__ float comp(const float4& v, int k) { return ((const float*)&v)[k]; }

// lerp paired entry (a01,a23,b01,b23) with half2 arithmetic -> fp32x4
__device__ __forceinline__ float4 lerp_p4(uint4 ab, __half2 f2) {
    __half2 a0 = *reinterpret_cast<__half2*>(&ab.x);
    __half2 a1 = *reinterpret_cast<__half2*>(&ab.y);
    __half2 b0 = *reinterpret_cast<__half2*>(&ab.z);
    __half2 b1 = *reinterpret_cast<__half2*>(&ab.w);
    __half2 w0 = __hfma2(f2, __hsub2(b0, a0), a0);
    __half2 w1 = __hfma2(f2, __hsub2(b1, a1), a1);
    float2 lo = __half22float2(w0), hi = __half22float2(w1);
    return make_float4(lo.x, lo.y, hi.x, hi.y);
}

// 16x16 output warp tile, K=16*KS, 2-pass: A bf16 x (Bhi + Blo).
template<int KS>
__device__ __forceinline__ void gemm16(
    uint32_t aH, uint32_t bH, uint32_t bL,
    int mr, int nc, int lane, float (*c)[4])
{
    const uint32_t aoff = (uint32_t)((mr + (lane & 7) + ((lane >> 3) & 1) * 8) * BSTR
                                     + ((lane >> 4) & 1) * 16);
    const uint32_t boff = (uint32_t)(((lane & 7) + ((lane >> 3) & 1) * 8) * BSTR
                                     + (nc + ((lane >> 4) & 1) * 8) * 2);
    #pragma unroll
    for (int ks = 0; ks < KS; ks++) {
        const uint32_t ao = aoff + ks * 32;
        const uint32_t bo = boff + ks * 16 * BSTR;
        uint32_t Ah[4], Bh[4], Bl[4];
        ldsm4(Ah, aH + ao);
        ldsm4t(Bh, bH + bo);
        mmabf(c[0], Ah, Bh); mmabf(c[1], Ah, Bh + 2);
        ldsm4t(Bl, bL + bo);
        mmabf(c[0], Ah, Bl); mmabf(c[1], Ah, Bl + 2);
    }
}

// ======= builder 1 (256 thr, 64 knots/CTA, 8 rows/warp), paired output ==========
constexpr int A_W1 = 0;          // 52x128
constexpr int A_W2 = 6656;       // 128x128
constexpr int A_F  = 23040;      // 64x52
constexpr int A_H1 = 26368;      // 64x128
constexpr int A_B1 = 34560;
constexpr int A_B2 = 34688;
constexpr int A_FLOATS = 34816;

__global__ void __launch_bounds__(256, 1)
build_table(const float* __restrict__ Wf1, const float* __restrict__ bf1,
            const float* __restrict__ Wf2, const float* __restrict__ bf2)
{
    extern __shared__ float sa[];
    const int tid = threadIdx.x, lane = tid & 31, w = tid >> 5;   // 8 warps
    const int layer = blockIdx.y;
    const int kb = blockIdx.x * 64;
    const int c4 = lane << 2;

    for (int idx = tid; idx < 52 * 128; idx += 256) {
        int k = idx >> 7, n = idx & 127;
        sa[A_W1 + idx] = (k < RR) ? Wf1[layer * RR * DD + k * DD + n] : 0.f;
    }
    for (int idx = tid; idx < 128 * 128; idx += 256)
        sa[A_W2 + idx] = Wf2[layer * DD * DD + idx];
    if (tid < 128) {
        sa[A_B1 + tid] = bf1[layer * DD + tid];
        sa[A_B2 + tid] = bf2[layer * DD + tid];
    }
    for (int idx = tid; idx < 64 * 52; idx += 256) {
        int row = idx / 52, r = idx - row * 52;
        float d = (float)(kb + row) * HSTEP;
        float t = d - (float)r * WIDTH;
        sa[A_F + idx] = (r < RR) ? __expf(COEFF * t * t) : 0.f;
    }
    __syncthreads();

    for (int blk = 0; blk < 2; blk++) {
        const int r0 = w * 8 + blk * 4;
        float4 ac0 = {0,0,0,0}, ac1 = {0,0,0,0}, ac2 = {0,0,0,0}, ac3 = {0,0,0,0};
        #pragma unroll
        for (int k = 0; k < 52; k += 4) {
            float4 a0 = *(const float4*)(sa + A_F + (r0 + 0) * 52 + k);
            float4 a1 = *(const float4*)(sa + A_F + (r0 + 1) * 52 + k);
            float4 a2 = *(const float4*)(sa + A_F + (r0 + 2) * 52 + k);
            float4 a3 = *(const float4*)(sa + A_F + (r0 + 3) * 52 + k);
            #pragma unroll
            for (int kk = 0; kk < 4; kk++) {
                float4 b = *(const float4*)(sa + A_W1 + (k + kk) * 128 + c4);
                fma4(ac0, comp(a0, kk), b); fma4(ac1, comp(a1, kk), b);
                fma4(ac2, comp(a2, kk), b); fma4(ac3, comp(a3, kk), b);
            }
        }
        float4 bb = *(const float4*)(sa + A_B1 + c4);
        float4* accs[4] = {&ac0, &ac1, &ac2, &ac3};
        #pragma unroll
        for (int m = 0; m < 4; m++) {
            float4 o;
            o.x = sspf(accs[m]->x + bb.x); o.y = sspf(accs[m]->y + bb.y);
            o.z = sspf(accs[m]->z + bb.z); o.w = sspf(accs[m]->w + bb.w);
            *(float4*)(sa + A_H1 + (r0 + m) * 128 + c4) = o;
        }
    }
    __syncthreads();

    char* gt = (char*)g_tab;
    for (int blk = 0; blk < 2; blk++) {
        const int r0 = w * 8 + blk * 4;
        float4 ac0 = {0,0,0,0}, ac1 = {0,0,0,0}, ac2 = {0,0,0,0}, ac3 = {0,0,0,0};
        #pragma unroll 4
        for (int k = 0; k < 128; k += 4) {
            float4 a0 = *(const float4*)(sa + A_H1 + (r0 + 0) * 128 + k);
            float4 a1 = *(const float4*)(sa + A_H1 + (r0 + 1) * 128 + k);
            float4 a2 = *(const float4*)(sa + A_H1 + (r0 + 2) * 128 + k);
            float4 a3 = *(const float4*)(sa + A_H1 + (r0 + 3) * 128 + k);
            #pragma unroll
            for (int kk = 0; kk < 4; kk++) {
                float4 b = *(const float4*)(sa + A_W2 + (k + kk) * 128 + c4);
                fma4(ac0, comp(a0, kk), b); fma4(ac1, comp(a1, kk), b);
                fma4(ac2, comp(a2, kk), b); fma4(ac3, comp(a3, kk), b);
            }
        }
        float4 bb = *(const float4*)(sa + A_B2 + c4);
        float4* accs[4] = {&ac0, &ac1, &ac2, &ac3};
        #pragma unroll
        for (int m = 0; m < 4; m++) {
            int rowg = kb + r0 + m;
            float d = (float)rowg * HSTEP;
            float rc = (d < CUTOFF) ? 0.5f * (__cosf(d * (PIF / CUTOFF)) + 1.f) : 0.f;
            float4 o;
            o.x = (accs[m]->x + bb.x) * rc; o.y = (accs[m]->y + bb.y) * rc;
            o.z = (accs[m]->z + bb.z) * rc; o.w = (accs[m]->w + bb.w) * rc;
            __half h0 = __float2half_rn(o.x), h1 = __float2half_rn(o.y);
            __half h2 = __float2half_rn(o.z), h3 = __float2half_rn(o.w);
            uint2 pk;
            pk.x = (uint32_t)__half_as_ushort(h0) | ((uint32_t)__half_as_ushort(h1) << 16);
            pk.y = (uint32_t)__half_as_ushort(h2) | ((uint32_t)__half_as_ushort(h3) << 16);
            size_t eb = ((size_t)layer * TKNOTS + rowg) * 512;
            *(uint2*)(gt + eb + lane * 16) = pk;                   // a-slot of entry rowg
            if (rowg > 0)
                *(uint2*)(gt + eb - 512 + lane * 16 + 8) = pk;     // b-slot of entry rowg-1
        }
    }
}

// ================= builder 2: split Wi/Wo1/Wo2 to bf16 hi/lo =================
__global__ void __launch_bounds__(1024, 1)
build_wsplit(const float* __restrict__ Wi,
             const float* __restrict__ Wo1,
             const float* __restrict__ Wo2)
{
    int idx = blockIdx.x * 1024 + threadIdx.x;
    const int TOT = 3 * NLAY * DD * (DD / 2);
    if (idx >= TOT) return;
    int mat = idx / (NLAY * DD * (DD / 2));
    int rem = idx - mat * (NLAY * DD * (DD / 2));
    const float* src = (mat == 0) ? Wi : (mat == 1) ? Wo1 : Wo2;
    float v0 = src[rem * 2];
    float v1 = src[rem * 2 + 1];
    uint32_t h0, l0, h1, l1;
    split2(v0, h0, l0); split2(v1, h1, l1);
    g_wh[idx] = h0 | (h1 << 16);
    g_wl[idx] = l0 | (l1 << 16);
}

// ================= main kernel: 2 molecules / CTA, 2-pass GEMMs =================
constexpr int SB_WBH  = 0;         // 128 x 272B = 34816  (Wi -> Wo1 -> Wo2)
constexpr int SB_WBL  = 34816;     // -> 69632
constexpr int SB_X    = 69632;     // 64x128 f32 = 32768 -> 102400
constexpr int SB_XF   = 102400;    // 32768 -> 135168 (head scratch later)
constexpr int SB_A1H  = 135168;    // 64 x 272B = 17408 -> 152576
constexpr int SB_A2H  = 152576;    // -> 169984
constexpr int SB_BO1  = 169984;    // 128 f32 -> 170496
constexpr int SB_BO2  = 170496;    // -> 171008
constexpr int SB_POS  = 171008;    // 192 f32 (pad 1024) -> 172032
constexpr int SB_KOFF = 172032;    // 1024 u32 -> 176128
constexpr int SB_FRACH= 176128;    // 1024 f16 -> 178176
constexpr int SB_PAIR = 178176;    // 512 u16 -> 179200
constexpr int SB_ENT  = 179200;    // 2 x 32 x 31 x 8B = 15872 -> 195072
constexpr int SMEM_BYTES = 195072;

__global__ void __launch_bounds__(NB, 1)
schnet_main(const int*   __restrict__ Z,   const float* __restrict__ pos,
            const float* __restrict__ emb,
            const float* __restrict__ bo1, const float* __restrict__ bo2,
            const float* __restrict__ Wh1, const float* __restrict__ bh1,
            const float* __restrict__ Wh2, const float* __restrict__ bh2,
            float* __restrict__ out)
{
    extern __shared__ __align__(1024) char smc[];
    float* Xs    = (float*)(smc + SB_X);
    float* XFs   = (float*)(smc + SB_XF);
    float* BO1s  = (float*)(smc + SB_BO1);
    float* BO2s  = (float*)(smc + SB_BO2);
    float* POSs  = (float*)(smc + SB_POS);
    uint32_t* KOFFs = (uint32_t*)(smc + SB_KOFF);
    __half*  FRACHs = (__half*)(smc + SB_FRACH);
    uint32_t* A1H32 = (uint32_t*)(smc + SB_A1H);
    uint32_t* A2H32 = (uint32_t*)(smc + SB_A2H);
    unsigned short* PAIRs = (unsigned short*)(smc + SB_PAIR);
    uint2* ENTs = (uint2*)(smc + SB_ENT);
    const uint32_t smb = smem_u32(smc);

    const int tid = threadIdx.x, lane = tid & 31, w = tid >> 5;
    const int blk = blockIdx.x;                  // molecule pair
    const int c4 = lane << 2;
    const int mr = (w & 3) * 16, nc0 = (w >> 2) * 32;   // HMMA: 64-row A, 2 col tiles

    // ---------- init ----------
    if (tid < 2 * NA * 3) POSs[tid] = pos[blk * 2 * NA * 3 + tid];
    {
        int p = tid;
        unsigned short pr = 0;
        if (p < NP) {
            int i = 0, base = 0;
            while (p >= base + (31 - i)) { base += 31 - i; i++; }
            int j = i + 1 + (p - base);
            pr = (unsigned short)((i << 5) | j);
        }
        if (tid < 512) PAIRs[tid] = pr;
    }
    for (int idx = tid; idx < 2 * NA * DD; idx += NB) {
        int a = idx >> 7, cc = idx & (DD - 1);
        Xs[idx] = emb[Z[blk * 2 * NA + a] * DD + cc];
    }
    __syncthreads();
    for (int idx = tid; idx < 1024; idx += NB) {
        int m = idx >> 9, p = idx & 511;
        uint32_t ko = 0;
        __half fh = __float2half(0.f);
        if (p < NP) {
            int pr = PAIRs[p]; int i = pr >> 5, j = pr & 31;
            const float* pm = POSs + m * NA * 3;
            float dx = pm[i*3+0] - pm[j*3+0];
            float dy = pm[i*3+1] - pm[j*3+1];
            float dz = pm[i*3+2] - pm[j*3+2];
            float d = sqrtf(dx*dx + dy*dy + dz*dz);
            float t = fminf(d * KSCALE, (float)(TKNOTS - 1));
            int kf = min((int)t, TKNOTS - 2);
            ko = (uint32_t)kf * 512u;            // byte offset of paired entry
            fh = __float2half(t - (float)kf);
        }
        KOFFs[idx] = ko;
        FRACHs[idx] = fh;
    }
    __syncthreads();
    // fused entry table: ENT[m][a][e] = {koff, frach | other<<16}
    for (int idx = tid; idx < 1984; idx += NB) {
        int m = (idx >= 992) ? 1 : 0;
        int rem = idx - m * 992;
        int a = rem / 31, e = rem - a * 31;
        int p, other;
        if (e < a) { int i = e; p = i * 31 - (i * (i - 1)) / 2 + (a - i - 1); other = i; }
        else       { int j = e + 1; p = a * 31 - (a * (a - 1)) / 2 + (j - a - 1); other = j; }
        uint2 v;
        v.x = KOFFs[m * 512 + p];
        v.y = (uint32_t)__half_as_ushort(FRACHs[m * 512 + p]) | ((uint32_t)other << 16);
        ENTs[idx] = v;
    }
    __syncthreads();

    // ---------- layers ----------
    const uint2* gh = (const uint2*)g_wh;
    const uint2* gl = (const uint2*)g_wl;
    for (int l = 0; l < NLAY; l++) {
        // phase 1: stage Wi -> WB; pack X (bf16) -> A1; biases
        {
            const int wbI = l * 4096;
            for (int idx = tid; idx < 4096; idx += NB) {
                int row = idx >> 5, n4 = idx & 31;
                *(uint2*)(smc + SB_WBH + row * BSTR + n4 * 8) = gh[wbI + idx];
                *(uint2*)(smc + SB_WBL + row * BSTR + n4 * 8) = gl[wbI + idx];
            }
            for (int idx = tid; idx < 4096; idx += NB) {
                int row = idx >> 6, n2 = idx & 63;
                float2 v = *(const float2*)(Xs + row * DD + n2 * 2);
                A1H32[row * 68 + n2] = packbf2(v.x, v.y);
            }
            if (tid < DD) {
                BO1s[tid] = bo1[l * DD + tid];
                BO2s[tid] = bo2[l * DD + tid];
            }
        }
        __syncthreads();
        // phase 2: in2f HMMA (64x128) -> XF
        {
            float c[2][2][4] = {{{0,0,0,0},{0,0,0,0}},{{0,0,0,0},{0,0,0,0}}};
            gemm16<8>(smb + SB_A1H, smb + SB_WBH, smb + SB_WBL, mr, nc0, lane, c[0]);
            gemm16<8>(smb + SB_A1H, smb + SB_WBH, smb + SB_WBL, mr, nc0 + 16, lane, c[1]);
            int r0 = mr + (lane >> 2);
            #pragma unroll
            for (int tI = 0; tI < 2; tI++) {
                int cb = nc0 + tI * 16 + (lane & 3) * 2;
                *(float2*)(XFs + r0 * DD + cb)           = make_float2(c[tI][0][0], c[tI][0][1]);
                *(float2*)(XFs + (r0 + 8) * DD + cb)     = make_float2(c[tI][0][2], c[tI][0][3]);
                *(float2*)(XFs + r0 * DD + cb + 8)       = make_float2(c[tI][1][0], c[tI][1][1]);
                *(float2*)(XFs + (r0 + 8) * DD + cb + 8) = make_float2(c[tI][1][2], c[tI][1][3]);
            }
        }
        __syncthreads();   // XF ready; WB (Wi) dead

        // phase 3: stage Wo1 -> WB (hidden), msg loop (4 atoms/warp), dump agg
        {
            const int wb1 = (NLAY + l) * 4096;
            for (int idx = tid; idx < 4096; idx += NB) {
                int row = idx >> 5, n4 = idx & 31;
                *(uint2*)(smc + SB_WBH + row * BSTR + n4 * 8) = gh[wb1 + idx];
                *(uint2*)(smc + SB_WBL + row * BSTR + n4 * 8) = gl[wb1 + idx];
            }
        }
        {
            const char* tabB = (const char*)g_tab + (size_t)l * TKNOTS * 512;
            const uint2* entA = ENTs;
            const uint2* entB = ENTs + 992;
            const int a0 = w, a1 = w + 16;
            const int lb = lane * 16;
            float4 acA0 = {0,0,0,0}, acA1 = {0,0,0,0};
            float4 acB0 = {0,0,0,0}, acB1 = {0,0,0,0};
            #pragma unroll 2
            for (int e = 0; e < 31; e++) {
                uint2 eA0 = entA[a0 * 31 + e];
                uint2 eA1 = entA[a1 * 31 + e];
                uint2 eB0 = entB[a0 * 31 + e];
                uint2 eB1 = entB[a1 * 31 + e];
                {
                    uint4 ab = *(const uint4*)(tabB + eA0.x + lb);
                    __half2 f2 = __half2half2(__ushort_as_half((unsigned short)(eA0.y & 0xffff)));
                    float4 wv = lerp_p4(ab, f2);
                    int o = (int)(eA0.y >> 16);
                    fma4v(acA0, wv, *(const float4*)(XFs + o * DD + c4));
                }
                {
                    uint4 ab = *(const uint4*)(tabB + eA1.x + lb);
                    __half2 f2 = __half2half2(__ushort_as_half((unsigned short)(eA1.y & 0xffff)));
                    float4 wv = lerp_p4(ab, f2);
                    int o = (int)(eA1.y >> 16);
                    fma4v(acA1, wv, *(const float4*)(XFs + o * DD + c4));
                }
                {
                    uint4 ab = *(const uint4*)(tabB + eB0.x + lb);
                    __half2 f2 = __half2half2(__ushort_as_half((unsigned short)(eB0.y & 0xffff)));
                    float4 wv = lerp_p4(ab, f2);
                    int o = (int)(eB0.y >> 16);
                    fma4v(acB0, wv, *(const float4*)(XFs + (NA + o) * DD + c4));
                }
                {
                    uint4 ab = *(const uint4*)(tabB + eB1.x + lb);
                    __half2 f2 = __half2half2(__ushort_as_half((unsigned short)(eB1.y & 0xffff)));
                    float4 wv = lerp_p4(ab, f2);
                    int o = (int)(eB1.y >> 16);
                    fma4v(acB1, wv, *(const float4*)(XFs + (NA + o) * DD + c4));
                }
            }
            float4* accs[4] = {&acA0, &acA1, &acB0, &acB1};
            int rows[4] = {w, w + 16, NA + w, NA + 16 + w};
            #pragma unroll
            for (int q = 0; q < 4; q++) {
                A1H32[rows[q] * 68 + lane * 2]     = packbf2(accs[q]->x, accs[q]->y);
                A1H32[rows[q] * 68 + lane * 2 + 1] = packbf2(accs[q]->z, accs[q]->w);
            }
        }
        __syncthreads();   // A1 ready; Wo1 staged
        // phase 4: f2out1: t1 = ssp(agg @ Wo1 + bo1) -> bf16 -> A2
        {
            float c[2][2][4] = {{{0,0,0,0},{0,0,0,0}},{{0,0,0,0},{0,0,0,0}}};
            gemm16<8>(smb + SB_A1H, smb + SB_WBH, smb + SB_WBL, mr, nc0, lane, c[0]);
            gemm16<8>(smb + SB_A1H, smb + SB_WBH, smb + SB_WBL, mr, nc0 + 16, lane, c[1]);
            int r0 = mr + (lane >> 2);
            #pragma unroll
            for (int tI = 0; tI < 2; tI++)
                #pragma unroll
                for (int ni = 0; ni < 2; ni++)
                    #pragma unroll
                    for (int h = 0; h < 2; h++) {
                        int row = r0 + h * 8;
                        int col = nc0 + tI * 16 + ni * 8 + (lane & 3) * 2;
                        float v0 = sspf(c[tI][ni][h*2+0] + BO1s[col]);
                        float v1 = sspf(c[tI][ni][h*2+1] + BO1s[col+1]);
                        A2H32[row * 68 + (col >> 1)] = packbf2(v0, v1);
                    }
        }
        __syncthreads();
        // phase 5: stage Wo2 -> WB
        {
            const int wb2 = (2 * NLAY + l) * 4096;
            for (int idx = tid; idx < 4096; idx += NB) {
                int row = idx >> 5, n4 = idx & 31;
                *(uint2*)(smc + SB_WBH + row * BSTR + n4 * 8) = gh[wb2 + idx];
                *(uint2*)(smc + SB_WBL + row * BSTR + n4 * 8) = gl[wb2 + idx];
            }
        }
        __syncthreads();
        // phase 6: f2out2 + residual: x += t1 @ Wo2 + bo2
        {
            float c[2][2][4] = {{{0,0,0,0},{0,0,0,0}},{{0,0,0,0},{0,0,0,0}}};
            gemm16<8>(smb + SB_A2H, smb + SB_WBH, smb + SB_WBL, mr, nc0, lane, c[0]);
            gemm16<8>(smb + SB_A2H, smb + SB_WBH, smb + SB_WBL, mr, nc0 + 16, lane, c[1]);
            int r0 = mr + (lane >> 2);
            #pragma unroll
            for (int tI = 0; tI < 2; tI++)
                #pragma unroll
                for (int ni = 0; ni < 2; ni++)
                    #pragma unroll
                    for (int h = 0; h < 2; h++) {
                        int row = r0 + h * 8;
                        int col = nc0 + tI * 16 + ni * 8 + (lane & 3) * 2;
                        float2 x = *(const float2*)(Xs + row * DD + col);
                        x.x += c[tI][ni][h*2+0] + BO2s[col];
                        x.y += c[tI][ni][h*2+1] + BO2s[col+1];
                        *(float2*)(Xs + row * DD + col) = x;
                    }
        }
        __syncthreads();
    }

    // ---------- readout head (scratch in XF region), 2 molecules ----------
    float* HD = XFs;
    if (tid < 256) {
        int m = tid >> 7, cc = tid & 127;
        float s = 0.f;
        #pragma unroll
        for (int i = 0; i < NA; i++) s += Xs[(m * NA + i) * DD + cc];
        HD[tid] = s;
    }
    __syncthreads();
    if (tid < 256) {
        int m = tid >> 7, cc = tid & 127;
        float acc = 0.f;
        #pragma unroll 8
        for (int k = 0; k < DD; k++) acc = fmaf(HD[m * DD + k], Wh1[k * DD + cc], acc);
        float hpre = acc + bh1[cc];
        float h = hpre / (1.f + __expf(-hpre));
        HD[256 + tid] = h * Wh2[cc];
    }
    __syncthreads();
    if (tid < 2) {
        float s = bh2[0];
        #pragma unroll 8
        for (int k = 0; k < DD; k++) s += HD[256 + tid * DD + k];
        out[blk * 2 + tid] = s;
    }
}

extern "C" void kernel_launch(void* const* d_in, const int* in_sizes, int n_in,
                              void* d_out, int out_size)
{
    const int*   Z   = (const int*)  d_in[0];
    const float* pos = (const float*)d_in[1];
    const float* emb = (const float*)d_in[6];
    const float* Wi  = (const float*)d_in[7];
    const float* Wf1 = (const float*)d_in[8];
    const float* bf1 = (const float*)d_in[9];
    const float* Wf2 = (const float*)d_in[10];
    const float* bf2 = (const float*)d_in[11];
    const float* Wo1 = (const float*)d_in[12];
    const float* bo1 = (const float*)d_in[13];
    const float* Wo2 = (const float*)d_in[14];
    const float* bo2 = (const float*)d_in[15];
    const float* Wh1 = (const float*)d_in[16];
    const float* bh1 = (const float*)d_in[17];
    const float* Wh2 = (const float*)d_in[18];
    const float* bh2 = (const float*)d_in[19];

    const int B = out_size;
    const int smemA = A_FLOATS * sizeof(float);
    cudaFuncSetAttribute(build_table,
                         cudaFuncAttributeMaxDynamicSharedMemorySize, smemA);
    cudaFuncSetAttribute(schnet_main,
                         cudaFuncAttributeMaxDynamicSharedMemorySize, SMEM_BYTES);

    build_table<<<dim3(TKNOTS / 64, NLAY), 256, smemA>>>(Wf1, bf1, Wf2, bf2);
    build_wsplit<<<(3 * NLAY * DD * (DD / 2) + 1023) / 1024, 1024>>>(Wi, Wo1, Wo2);
    schnet_main<<<B / 2, NB, SMEM_BYTES>>>(Z, pos, emb, bo1, bo2,
                                           Wh1, bh1, Wh2, bh2, (float*)d_out);
}

// round 17
// speedup vs baseline: 1.3105x; 1.1399x over previous
#include <cuda_runtime.h>
#include <cuda_bf16.h>
#include <cuda_fp16.h>
#include <cstdint>

#define NB 512
constexpr int NA = 32;
constexpr int DD = 128;
constexpr int RR = 50;
constexpr int NP = 496;
constexpr int NLAY = 6;
constexpr int TKNOTS = 1024;
constexpr float CUTOFF = 5.0f;
constexpr float WIDTH  = CUTOFF / (RR - 1);
constexpr float COEFF  = -0.5f / (WIDTH * WIDTH);
constexpr float LN2    = 0.69314718055994531f;
constexpr float PIF    = 3.14159265358979323846f;
constexpr float HSTEP  = CUTOFF / (TKNOTS - 1);
constexpr float KSCALE = (TKNOTS - 1) / CUTOFF;
constexpr int BSTR = 272;    // bf16 operand row stride (bytes) = 136 halves

// ---------------- device globals ----------------
// paired filter table: entry k holds (W_k, W_{k+1}) interleaved per 4-ch group.
__device__ __half   g_tab[(size_t)NLAY * TKNOTS * 256];
__device__ uint32_t g_wh[3 * NLAY * DD * (DD / 2)];               // bf16 packed pairs

// ---------------- helpers ----------------
__device__ __forceinline__ uint32_t smem_u32(const void* p) {
    uint32_t a;
    asm("{ .reg .u64 t; cvta.to.shared.u64 t, %1; cvt.u32.u64 %0, t; }"
        : "=r"(a) : "l"(p));
    return a;
}
__device__ __forceinline__ void ldsm4(uint32_t* r, uint32_t a) {
    asm volatile("ldmatrix.sync.aligned.m8n8.x4.shared.b16 {%0,%1,%2,%3}, [%4];"
        : "=r"(r[0]), "=r"(r[1]), "=r"(r[2]), "=r"(r[3]) : "r"(a));
}
__device__ __forceinline__ void ldsm4t(uint32_t* r, uint32_t a) {
    asm volatile("ldmatrix.sync.aligned.m8n8.x4.trans.shared.b16 {%0,%1,%2,%3}, [%4];"
        : "=r"(r[0]), "=r"(r[1]), "=r"(r[2]), "=r"(r[3]) : "r"(a));
}
__device__ __forceinline__ void mmabf(float* c, const uint32_t* a, const uint32_t* b) {
    asm volatile("mma.sync.aligned.m16n8k16.row.col.f32.bf16.bf16.f32 "
        "{%0,%1,%2,%3}, {%4,%5,%6,%7}, {%8,%9}, {%0,%1,%2,%3};"
        : "+f"(c[0]), "+f"(c[1]), "+f"(c[2]), "+f"(c[3])
        : "r"(a[0]), "r"(a[1]), "r"(a[2]), "r"(a[3]), "r"(b[0]), "r"(b[1]));
}
__device__ __forceinline__ uint32_t packbf2(float x, float y) {   // bf16(x) | bf16(y)<<16
    uint32_t hx = (uint32_t)__bfloat16_as_ushort(__float2bfloat16(x));
    uint32_t hy = (uint32_t)__bfloat16_as_ushort(__float2bfloat16(y));
    return hx | (hy << 16);
}
__device__ __forceinline__ float sspf(float x) {
    float r = __logf(fmaf(0.5f, __expf(x), 0.5f));
    return (x > 20.f) ? x - LN2 : r;
}
__device__ __forceinline__ void fma4(float4& a, float s, const float4& b) {
    a.x = fmaf(s, b.x, a.x); a.y = fmaf(s, b.y, a.y);
    a.z = fmaf(s, b.z, a.z); a.w = fmaf(s, b.w, a.w);
}
__device__ __forceinline__ void fma4v(float4& a, const float4& s, const float4& b) {
    a.x = fmaf(s.x, b.x, a.x); a.y = fmaf(s.y, b.y, a.y);
    a.z = fmaf(s.z, b.z, a.z); a.w = fmaf(s.w, b.w, a.w);
}
__device__ __forceinline__ float comp(const float4& v, int k) { return ((const float*)&v)[k]; }

// lerp paired entry (a01,a23,b01,b23) with half2 arithmetic -> fp32x4
__device__ __forceinline__ float4 lerp_p4(uint4 ab, __half2 f2) {
    __half2 a0 = *reinterpret_cast<__half2*>(&ab.x);
    __half2 a1 = *reinterpret_cast<__half2*>(&ab.y);
    __half2 b0 = *reinterpret_cast<__half2*>(&ab.z);
    __half2 b1 = *reinterpret_cast<__half2*>(&ab.w);
    __half2 w0 = __hfma2(f2, __hsub2(b0, a0), a0);
    __half2 w1 = __hfma2(f2, __hsub2(b1, a1), a1);
    float2 lo = __half22float2(w0), hi = __half22float2(w1);
    return make_float4(lo.x, lo.y, hi.x, hi.y);
}

// 16x16 output warp tile, K=16*KS, plain bf16 x bf16.
template<int KS>
__device__ __forceinline__ void gemm16(
    uint32_t aH, uint32_t bH,
    int mr, int nc, int lane, float (*c)[4])
{
    const uint32_t aoff = (uint32_t)((mr + (lane & 7) + ((lane >> 3) & 1) * 8) * BSTR
                                     + ((lane >> 4) & 1) * 16);
    const uint32_t boff = (uint32_t)(((lane & 7) + ((lane >> 3) & 1) * 8) * BSTR
                                     + (nc + ((lane >> 4) & 1) * 8) * 2);
    #pragma unroll
    for (int ks = 0; ks < KS; ks++) {
        const uint32_t ao = aoff + ks * 32;
        const uint32_t bo = boff + ks * 16 * BSTR;
        uint32_t Ah[4], Bh[4];
        ldsm4(Ah, aH + ao);
        ldsm4t(Bh, bH + bo);
        mmabf(c[0], Ah, Bh); mmabf(c[1], Ah, Bh + 2);
    }
}

// ======= builder 1 (256 thr, 64 knots/CTA, 8 rows/warp), paired output ==========
constexpr int A_W1 = 0;          // 52x128
constexpr int A_W2 = 6656;       // 128x128
constexpr int A_F  = 23040;      // 64x52
constexpr int A_H1 = 26368;      // 64x128
constexpr int A_B1 = 34560;
constexpr int A_B2 = 34688;
constexpr int A_FLOATS = 34816;

__global__ void __launch_bounds__(256, 1)
build_table(const float* __restrict__ Wf1, const float* __restrict__ bf1,
            const float* __restrict__ Wf2, const float* __restrict__ bf2)
{
    extern __shared__ float sa[];
    const int tid = threadIdx.x, lane = tid & 31, w = tid >> 5;   // 8 warps
    const int layer = blockIdx.y;
    const int kb = blockIdx.x * 64;
    const int c4 = lane << 2;

    for (int idx = tid; idx < 52 * 128; idx += 256) {
        int k = idx >> 7, n = idx & 127;
        sa[A_W1 + idx] = (k < RR) ? Wf1[layer * RR * DD + k * DD + n] : 0.f;
    }
    for (int idx = tid; idx < 128 * 128; idx += 256)
        sa[A_W2 + idx] = Wf2[layer * DD * DD + idx];
    if (tid < 128) {
        sa[A_B1 + tid] = bf1[layer * DD + tid];
        sa[A_B2 + tid] = bf2[layer * DD + tid];
    }
    for (int idx = tid; idx < 64 * 52; idx += 256) {
        int row = idx / 52, r = idx - row * 52;
        float d = (float)(kb + row) * HSTEP;
        float t = d - (float)r * WIDTH;
        sa[A_F + idx] = (r < RR) ? __expf(COEFF * t * t) : 0.f;
    }
    __syncthreads();

    for (int blk = 0; blk < 2; blk++) {
        const int r0 = w * 8 + blk * 4;
        float4 ac0 = {0,0,0,0}, ac1 = {0,0,0,0}, ac2 = {0,0,0,0}, ac3 = {0,0,0,0};
        #pragma unroll
        for (int k = 0; k < 52; k += 4) {
            float4 a0 = *(const float4*)(sa + A_F + (r0 + 0) * 52 + k);
            float4 a1 = *(const float4*)(sa + A_F + (r0 + 1) * 52 + k);
            float4 a2 = *(const float4*)(sa + A_F + (r0 + 2) * 52 + k);
            float4 a3 = *(const float4*)(sa + A_F + (r0 + 3) * 52 + k);
            #pragma unroll
            for (int kk = 0; kk < 4; kk++) {
                float4 b = *(const float4*)(sa + A_W1 + (k + kk) * 128 + c4);
                fma4(ac0, comp(a0, kk), b); fma4(ac1, comp(a1, kk), b);
                fma4(ac2, comp(a2, kk), b); fma4(ac3, comp(a3, kk), b);
            }
        }
        float4 bb = *(const float4*)(sa + A_B1 + c4);
        float4* accs[4] = {&ac0, &ac1, &ac2, &ac3};
        #pragma unroll
        for (int m = 0; m < 4; m++) {
            float4 o;
            o.x = sspf(accs[m]->x + bb.x); o.y = sspf(accs[m]->y + bb.y);
            o.z = sspf(accs[m]->z + bb.z); o.w = sspf(accs[m]->w + bb.w);
            *(float4*)(sa + A_H1 + (r0 + m) * 128 + c4) = o;
        }
    }
    __syncthreads();

    char* gt = (char*)g_tab;
    for (int blk = 0; blk < 2; blk++) {
        const int r0 = w * 8 + blk * 4;
        float4 ac0 = {0,0,0,0}, ac1 = {0,0,0,0}, ac2 = {0,0,0,0}, ac3 = {0,0,0,0};
        #pragma unroll 4
        for (int k = 0; k < 128; k += 4) {
            float4 a0 = *(const float4*)(sa + A_H1 + (r0 + 0) * 128 + k);
            float4 a1 = *(const float4*)(sa + A_H1 + (r0 + 1) * 128 + k);
            float4 a2 = *(const float4*)(sa + A_H1 + (r0 + 2) * 128 + k);
            float4 a3 = *(const float4*)(sa + A_H1 + (r0 + 3) * 128 + k);
            #pragma unroll
            for (int kk = 0; kk < 4; kk++) {
                float4 b = *(const float4*)(sa + A_W2 + (k + kk) * 128 + c4);
                fma4(ac0, comp(a0, kk), b); fma4(ac1, comp(a1, kk), b);
                fma4(ac2, comp(a2, kk), b); fma4(ac3, comp(a3, kk), b);
            }
        }
        float4 bb = *(const float4*)(sa + A_B2 + c4);
        float4* accs[4] = {&ac0, &ac1, &ac2, &ac3};
        #pragma unroll
        for (int m = 0; m < 4; m++) {
            int rowg = kb + r0 + m;
            float d = (float)rowg * HSTEP;
            float rc = (d < CUTOFF) ? 0.5f * (__cosf(d * (PIF / CUTOFF)) + 1.f) : 0.f;
            float4 o;
            o.x = (accs[m]->x + bb.x) * rc; o.y = (accs[m]->y + bb.y) * rc;
            o.z = (accs[m]->z + bb.z) * rc; o.w = (accs[m]->w + bb.w) * rc;
            __half h0 = __float2half_rn(o.x), h1 = __float2half_rn(o.y);
            __half h2 = __float2half_rn(o.z), h3 = __float2half_rn(o.w);
            uint2 pk;
            pk.x = (uint32_t)__half_as_ushort(h0) | ((uint32_t)__half_as_ushort(h1) << 16);
            pk.y = (uint32_t)__half_as_ushort(h2) | ((uint32_t)__half_as_ushort(h3) << 16);
            size_t eb = ((size_t)layer * TKNOTS + rowg) * 512;
            *(uint2*)(gt + eb + lane * 16) = pk;                   // a-slot of entry rowg
            if (rowg > 0)
                *(uint2*)(gt + eb - 512 + lane * 16 + 8) = pk;     // b-slot of entry rowg-1
        }
    }
}

// ================= builder 2: Wi/Wo1/Wo2 -> bf16 packed =================
__global__ void __launch_bounds__(1024, 1)
build_wsplit(const float* __restrict__ Wi,
             const float* __restrict__ Wo1,
             const float* __restrict__ Wo2)
{
    int idx = blockIdx.x * 1024 + threadIdx.x;
    const int TOT = 3 * NLAY * DD * (DD / 2);
    if (idx >= TOT) return;
    int mat = idx / (NLAY * DD * (DD / 2));
    int rem = idx - mat * (NLAY * DD * (DD / 2));
    const float* src = (mat == 0) ? Wi : (mat == 1) ? Wo1 : Wo2;
    g_wh[idx] = packbf2(src[rem * 2], src[rem * 2 + 1]);
}

// ================= main kernel: 2 molecules / CTA, 1-pass bf16 GEMMs ==========
constexpr int SB_WBH  = 0;         // 128 x 272B = 34816  (Wi -> Wo1 -> Wo2)
constexpr int SB_X    = 34816;     // 64x128 f32 = 32768 -> 67584
constexpr int SB_XF   = 67584;     // 32768 -> 100352 (head scratch later)
constexpr int SB_A1H  = 100352;    // 64 x 272B = 17408 -> 117760
constexpr int SB_A2H  = 117760;    // -> 135168
constexpr int SB_BO1  = 135168;    // 128 f32 -> 135680
constexpr int SB_BO2  = 135680;    // -> 136192
constexpr int SB_POS  = 136192;    // 192 f32 (pad 1024) -> 137216
constexpr int SB_KOFF = 137216;    // 1024 u32 -> 141312
constexpr int SB_FRACH= 141312;    // 1024 f16 -> 143360
constexpr int SB_PAIR = 143360;    // 512 u16 -> 144384
constexpr int SB_ENT  = 144384;    // 2 x 32 x 31 x 8B = 15872 -> 160256
constexpr int SMEM_BYTES = 160256;

__global__ void __launch_bounds__(NB, 1)
schnet_main(const int*   __restrict__ Z,   const float* __restrict__ pos,
            const float* __restrict__ emb,
            const float* __restrict__ bo1, const float* __restrict__ bo2,
            const float* __restrict__ Wh1, const float* __restrict__ bh1,
            const float* __restrict__ Wh2, const float* __restrict__ bh2,
            float* __restrict__ out)
{
    extern __shared__ __align__(1024) char smc[];
    float* Xs    = (float*)(smc + SB_X);
    float* XFs   = (float*)(smc + SB_XF);
    float* BO1s  = (float*)(smc + SB_BO1);
    float* BO2s  = (float*)(smc + SB_BO2);
    float* POSs  = (float*)(smc + SB_POS);
    uint32_t* KOFFs = (uint32_t*)(smc + SB_KOFF);
    __half*  FRACHs = (__half*)(smc + SB_FRACH);
    uint32_t* A1H32 = (uint32_t*)(smc + SB_A1H);
    uint32_t* A2H32 = (uint32_t*)(smc + SB_A2H);
    unsigned short* PAIRs = (unsigned short*)(smc + SB_PAIR);
    uint2* ENTs = (uint2*)(smc + SB_ENT);
    const uint32_t smb = smem_u32(smc);

    const int tid = threadIdx.x, lane = tid & 31, w = tid >> 5;
    const int blk = blockIdx.x;                  // molecule pair
    const int c4 = lane << 2;
    const int mr = (w & 3) * 16, nc0 = (w >> 2) * 32;   // HMMA: 64-row A, 2 col tiles

    // ---------- init ----------
    if (tid < 2 * NA * 3) POSs[tid] = pos[blk * 2 * NA * 3 + tid];
    {
        int p = tid;
        unsigned short pr = 0;
        if (p < NP) {
            int i = 0, base = 0;
            while (p >= base + (31 - i)) { base += 31 - i; i++; }
            int j = i + 1 + (p - base);
            pr = (unsigned short)((i << 5) | j);
        }
        if (tid < 512) PAIRs[tid] = pr;
    }
    for (int idx = tid; idx < 2 * NA * DD; idx += NB) {
        int a = idx >> 7, cc = idx & (DD - 1);
        Xs[idx] = emb[Z[blk * 2 * NA + a] * DD + cc];
    }
    __syncthreads();
    for (int idx = tid; idx < 1024; idx += NB) {
        int m = idx >> 9, p = idx & 511;
        uint32_t ko = 0;
        __half fh = __float2half(0.f);
        if (p < NP) {
            int pr = PAIRs[p]; int i = pr >> 5, j = pr & 31;
            const float* pm = POSs + m * NA * 3;
            float dx = pm[i*3+0] - pm[j*3+0];
            float dy = pm[i*3+1] - pm[j*3+1];
            float dz = pm[i*3+2] - pm[j*3+2];
            float d = sqrtf(dx*dx + dy*dy + dz*dz);
            float t = fminf(d * KSCALE, (float)(TKNOTS - 1));
            int kf = min((int)t, TKNOTS - 2);
            ko = (uint32_t)kf * 512u;            // byte offset of paired entry
            fh = __float2half(t - (float)kf);
        }
        KOFFs[idx] = ko;
        FRACHs[idx] = fh;
    }
    __syncthreads();
    // fused entry table: ENT[m][a][e] = {koff, frach | other<<16}
    for (int idx = tid; idx < 1984; idx += NB) {
        int m = (idx >= 992) ? 1 : 0;
        int rem = idx - m * 992;
        int a = rem / 31, e = rem - a * 31;
        int p, other;
        if (e < a) { int i = e; p = i * 31 - (i * (i - 1)) / 2 + (a - i - 1); other = i; }
        else       { int j = e + 1; p = a * 31 - (a * (a - 1)) / 2 + (j - a - 1); other = j; }
        uint2 v;
        v.x = KOFFs[m * 512 + p];
        v.y = (uint32_t)__half_as_ushort(FRACHs[m * 512 + p]) | ((uint32_t)other << 16);
        ENTs[idx] = v;
    }
    __syncthreads();

    // ---------- layers ----------
    const uint2* gh = (const uint2*)g_wh;
    for (int l = 0; l < NLAY; l++) {
        // phase 1: stage Wi -> WB; pack X (bf16) -> A1; biases
        {
            const int wbI = l * 4096;
            for (int idx = tid; idx < 4096; idx += NB) {
                int row = idx >> 5, n4 = idx & 31;
                *(uint2*)(smc + SB_WBH + row * BSTR + n4 * 8) = gh[wbI + idx];
            }
            for (int idx = tid; idx < 4096; idx += NB) {
                int row = idx >> 6, n2 = idx & 63;
                float2 v = *(const float2*)(Xs + row * DD + n2 * 2);
                A1H32[row * 68 + n2] = packbf2(v.x, v.y);
            }
            if (tid < DD) {
                BO1s[tid] = bo1[l * DD + tid];
                BO2s[tid] = bo2[l * DD + tid];
            }
        }
        __syncthreads();
        // phase 2: in2f HMMA (64x128) -> XF
        {
            float c[2][2][4] = {{{0,0,0,0},{0,0,0,0}},{{0,0,0,0},{0,0,0,0}}};
            gemm16<8>(smb + SB_A1H, smb + SB_WBH, mr, nc0, lane, c[0]);
            gemm16<8>(smb + SB_A1H, smb + SB_WBH, mr, nc0 + 16, lane, c[1]);
            int r0 = mr + (lane >> 2);
            #pragma unroll
            for (int tI = 0; tI < 2; tI++) {
                int cb = nc0 + tI * 16 + (lane & 3) * 2;
                *(float2*)(XFs + r0 * DD + cb)           = make_float2(c[tI][0][0], c[tI][0][1]);
                *(float2*)(XFs + (r0 + 8) * DD + cb)     = make_float2(c[tI][0][2], c[tI][0][3]);
                *(float2*)(XFs + r0 * DD + cb + 8)       = make_float2(c[tI][1][0], c[tI][1][1]);
                *(float2*)(XFs + (r0 + 8) * DD + cb + 8) = make_float2(c[tI][1][2], c[tI][1][3]);
            }
        }
        __syncthreads();   // XF ready; WB (Wi) dead

        // phase 3: stage Wo1 -> WB (hidden), msg loop (4 atoms/warp), dump agg
        {
            const int wb1 = (NLAY + l) * 4096;
            for (int idx = tid; idx < 4096; idx += NB) {
                int row = idx >> 5, n4 = idx & 31;
                *(uint2*)(smc + SB_WBH + row * BSTR + n4 * 8) = gh[wb1 + idx];
            }
        }
        {
            const char* tabB = (const char*)g_tab + (size_t)l * TKNOTS * 512;
            const uint2* entA = ENTs;
            const uint2* entB = ENTs + 992;
            const int a0 = w, a1 = w + 16;
            const int lb = lane * 16;
            float4 acA0 = {0,0,0,0}, acA1 = {0,0,0,0};
            float4 acB0 = {0,0,0,0}, acB1 = {0,0,0,0};
            #pragma unroll 2
            for (int e = 0; e < 31; e++) {
                uint2 eA0 = entA[a0 * 31 + e];
                uint2 eA1 = entA[a1 * 31 + e];
                uint2 eB0 = entB[a0 * 31 + e];
                uint2 eB1 = entB[a1 * 31 + e];
                {
                    uint4 ab = *(const uint4*)(tabB + eA0.x + lb);
                    __half2 f2 = __half2half2(__ushort_as_half((unsigned short)(eA0.y & 0xffff)));
                    float4 wv = lerp_p4(ab, f2);
                    int o = (int)(eA0.y >> 16);
                    fma4v(acA0, wv, *(const float4*)(XFs + o * DD + c4));
                }
                {
                    uint4 ab = *(const uint4*)(tabB + eA1.x + lb);
                    __half2 f2 = __half2half2(__ushort_as_half((unsigned short)(eA1.y & 0xffff)));
                    float4 wv = lerp_p4(ab, f2);
                    int o = (int)(eA1.y >> 16);
                    fma4v(acA1, wv, *(const float4*)(XFs + o * DD + c4));
                }
                {
                    uint4 ab = *(const uint4*)(tabB + eB0.x + lb);
                    __half2 f2 = __half2half2(__ushort_as_half((unsigned short)(eB0.y & 0xffff)));
                    float4 wv = lerp_p4(ab, f2);
                    int o = (int)(eB0.y >> 16);
                    fma4v(acB0, wv, *(const float4*)(XFs + (NA + o) * DD + c4));
                }
                {
                    uint4 ab = *(const uint4*)(tabB + eB1.x + lb);
                    __half2 f2 = __half2half2(__ushort_as_half((unsigned short)(eB1.y & 0xffff)));
                    float4 wv = lerp_p4(ab, f2);
                    int o = (int)(eB1.y >> 16);
                    fma4v(acB1, wv, *(const float4*)(XFs + (NA + o) * DD + c4));
                }
            }
            float4* accs[4] = {&acA0, &acA1, &acB0, &acB1};
            int rows[4] = {w, w + 16, NA + w, NA + 16 + w};
            #pragma unroll
            for (int q = 0; q < 4; q++) {
                A1H32[rows[q] * 68 + lane * 2]     = packbf2(accs[q]->x, accs[q]->y);
                A1H32[rows[q] * 68 + lane * 2 + 1] = packbf2(accs[q]->z, accs[q]->w);
            }
        }
        __syncthreads();   // A1 ready; Wo1 staged
        // phase 4: f2out1: t1 = ssp(agg @ Wo1 + bo1) -> bf16 -> A2
        {
            float c[2][2][4] = {{{0,0,0,0},{0,0,0,0}},{{0,0,0,0},{0,0,0,0}}};
            gemm16<8>(smb + SB_A1H, smb + SB_WBH, mr, nc0, lane, c[0]);
            gemm16<8>(smb + SB_A1H, smb + SB_WBH, mr, nc0 + 16, lane, c[1]);
            int r0 = mr + (lane >> 2);
            #pragma unroll
            for (int tI = 0; tI < 2; tI++)
                #pragma unroll
                for (int ni = 0; ni < 2; ni++)
                    #pragma unroll
                    for (int h = 0; h < 2; h++) {
                        int row = r0 + h * 8;
                        int col = nc0 + tI * 16 + ni * 8 + (lane & 3) * 2;
                        float v0 = sspf(c[tI][ni][h*2+0] + BO1s[col]);
                        float v1 = sspf(c[tI][ni][h*2+1] + BO1s[col+1]);
                        A2H32[row * 68 + (col >> 1)] = packbf2(v0, v1);
                    }
        }
        __syncthreads();
        // phase 5: stage Wo2 -> WB
        {
            const int wb2 = (2 * NLAY + l) * 4096;
            for (int idx = tid; idx < 4096; idx += NB) {
                int row = idx >> 5, n4 = idx & 31;
                *(uint2*)(smc + SB_WBH + row * BSTR + n4 * 8) = gh[wb2 + idx];
            }
        }
        __syncthreads();
        // phase 6: f2out2 + residual: x += t1 @ Wo2 + bo2
        {
            float c[2][2][4] = {{{0,0,0,0},{0,0,0,0}},{{0,0,0,0},{0,0,0,0}}};
            gemm16<8>(smb + SB_A2H, smb + SB_WBH, mr, nc0, lane, c[0]);
            gemm16<8>(smb + SB_A2H, smb + SB_WBH, mr, nc0 + 16, lane, c[1]);
            int r0 = mr + (lane >> 2);
            #pragma unroll
            for (int tI = 0; tI < 2; tI++)
                #pragma unroll
                for (int ni = 0; ni < 2; ni++)
                    #pragma unroll
                    for (int h = 0; h < 2; h++) {
                        int row = r0 + h * 8;
                        int col = nc0 + tI * 16 + ni * 8 + (lane & 3) * 2;
                        float2 x = *(const float2*)(Xs + row * DD + col);
                        x.x += c[tI][ni][h*2+0] + BO2s[col];
                        x.y += c[tI][ni][h*2+1] + BO2s[col+1];
                        *(float2*)(Xs + row * DD + col) = x;
                    }
        }
        __syncthreads();
    }

    // ---------- readout head (scratch in XF region), 2 molecules ----------
    float* HD = XFs;
    if (tid < 256) {
        int m = tid >> 7, cc = tid & 127;
        float s = 0.f;
        #pragma unroll
        for (int i = 0; i < NA; i++) s += Xs[(m * NA + i) * DD + cc];
        HD[tid] = s;
    }
    __syncthreads();
    if (tid < 256) {
        int m = tid >> 7, cc = tid & 127;
        float acc = 0.f;
        #pragma unroll 8
        for (int k = 0; k < DD; k++) acc = fmaf(HD[m * DD + k], Wh1[k * DD + cc], acc);
        float hpre = acc + bh1[cc];
        float h = hpre / (1.f + __expf(-hpre));
        HD[256 + tid] = h * Wh2[cc];
    }
    __syncthreads();
    if (tid < 2) {
        float s = bh2[0];
        #pragma unroll 8
        for (int k = 0; k < DD; k++) s += HD[256 + tid * DD + k];
        out[blk * 2 + tid] = s;
    }
}

extern "C" void kernel_launch(void* const* d_in, const int* in_sizes, int n_in,
                              void* d_out, int out_size)
{
    const int*   Z   = (const int*)  d_in[0];
    const float* pos = (const float*)d_in[1];
    const float* emb = (const float*)d_in[6];
    const float* Wi  = (const float*)d_in[7];
    const float* Wf1 = (const float*)d_in[8];
    const float* bf1 = (const float*)d_in[9];
    const float* Wf2 = (const float*)d_in[10];
    const float* bf2 = (const float*)d_in[11];
    const float* Wo1 = (const float*)d_in[12];
    const float* bo1 = (const float*)d_in[13];
    const float* Wo2 = (const float*)d_in[14];
    const float* bo2 = (const float*)d_in[15];
    const float* Wh1 = (const float*)d_in[16];
    const float* bh1 = (const float*)d_in[17];
    const float* Wh2 = (const float*)d_in[18];
    const float* bh2 = (const float*)d_in[19];

    const int B = out_size;
    const int smemA = A_FLOATS * sizeof(float);
    cudaFuncSetAttribute(build_table,
                         cudaFuncAttributeMaxDynamicSharedMemorySize, smemA);
    cudaFuncSetAttribute(schnet_main,
                         cudaFuncAttributeMaxDynamicSharedMemorySize, SMEM_BYTES);

    build_table<<<dim3(TKNOTS / 64, NLAY), 256, smemA>>>(Wf1, bf1, Wf2, bf2);
    build_wsplit<<<(3 * NLAY * DD * (DD / 2) + 1023) / 1024, 1024>>>(Wi, Wo1, Wo2);
    schnet_main<<<B / 2, NB, SMEM_BYTES>>>(Z, pos, emb, bo1, bo2,
                                           Wh1, bh1, Wh2, bh2, (float*)d_out);
}